// round 15
// baseline (speedup 1.0000x reference)
#include <cuda_runtime.h>
#include <cuda_bf16.h>
#include <math.h>
#include <stdint.h>

#define LQ 8000
#define LPAD 8192
#define NTL 63      // 128-row tiles (compression/expansion path)
#define NTL2 125    // 64-row tiles (pointwise path; 125*64 = 8000 exactly)

// ---------------- device scratch (no allocation allowed) ----------------
__device__ float g_buf0[4 * LPAD * 128];                // activation ping [b][l][c]
__device__ float g_buf1[4 * LPAD * 128];                // activation pong
__device__ __nv_bfloat16 g_xhi[4 * NTL * 4 * 16384];    // xT split tiles (128-row)
__device__ __nv_bfloat16 g_xlo[4 * NTL * 4 * 16384];
__device__ __nv_bfloat16 g_hhi[4 * NTL * 16384];        // conv/final split tiles
__device__ __nv_bfloat16 g_hlo[4 * NTL * 16384];
__device__ __nv_bfloat16 g_cwh[4 * 16384];              // compression W tiles
__device__ __nv_bfloat16 g_cwl[4 * 16384];
__device__ __nv_bfloat16 g_pwh[24 * 16384];             // pointwise W tiles
__device__ __nv_bfloat16 g_pwl[24 * 16384];
__device__ __nv_bfloat16 g_ewh[8 * 16384];              // expansion W tiles
__device__ __nv_bfloat16 g_ewl[8 * 16384];
__device__ float g_wb[128], g_wgs[128];
__device__ float g_pwb[24 * 128], g_pwgs[24 * 128];
__device__ float g_partx[4 * 512 * 2];
__device__ float g_partc[4 * NTL2 * 2];

// ---------------- helpers ----------------
__device__ __forceinline__ int swz_half(int row, int c) {
    return row * 128 + ((((c >> 3) ^ (row & 7)) << 3) | (c & 7));
}
__device__ __forceinline__ uint32_t smem_u32(const void* p) {
    uint32_t a;
    asm("{ .reg .u64 t; cvta.to.shared.u64 t, %1; cvt.u32.u64 %0, t; }" : "=r"(a) : "l"(p));
    return a;
}
__device__ __forceinline__ void cp16(uint32_t dst, const void* src) {
    asm volatile("cp.async.cg.shared.global [%0], [%1], 16;" :: "r"(dst), "l"(src));
}
__device__ __forceinline__ void ldsm4(uint32_t* r, uint32_t addr) {
    asm volatile("ldmatrix.sync.aligned.m8n8.x4.shared.b16 {%0,%1,%2,%3}, [%4];"
                 : "=r"(r[0]), "=r"(r[1]), "=r"(r[2]), "=r"(r[3]) : "r"(addr));
}
__device__ __forceinline__ void mma16816(float* c, const uint32_t* a,
                                         uint32_t b0, uint32_t b1) {
    asm volatile(
        "mma.sync.aligned.m16n8k16.row.col.f32.bf16.bf16.f32 "
        "{%0,%1,%2,%3}, {%4,%5,%6,%7}, {%8,%9}, {%0,%1,%2,%3};"
        : "+f"(c[0]), "+f"(c[1]), "+f"(c[2]), "+f"(c[3])
        : "r"(a[0]), "r"(a[1]), "r"(a[2]), "r"(a[3]), "r"(b0), "r"(b1));
}

// ---------------- weight prep ----------------
__global__ void comp_img_kernel(const float* __restrict__ w, const float* __restrict__ g,
                                __nv_bfloat16* __restrict__ ih, __nv_bfloat16* __restrict__ il) {
    int idx = blockIdx.x * 256 + threadIdx.x;
    int n = idx >> 7, o = idx & 127;
    float wv = w[o * 512 + n] * g[n];
    __nv_bfloat16 hi = __float2bfloat16(wv);
    int pos = (n >> 7) * 16384 + swz_half(o, n & 127);
    ih[pos] = hi;
    il[pos] = __float2bfloat16(wv - __bfloat162float(hi));
}
__global__ void sums_wg_kernel(const float* __restrict__ w, const float* __restrict__ g,
                               const float* __restrict__ beta,
                               float* __restrict__ wb, float* __restrict__ wgs) {
    int o = blockIdx.x, tid = threadIdx.x;
    float w1 = w[o * 512 + tid], w2 = w[o * 512 + tid + 256];
    float sb = w1 * beta[tid] + w2 * beta[tid + 256];
    float sg = w1 * g[tid] + w2 * g[tid + 256];
    __shared__ float r1[256], r2[256];
    r1[tid] = sb; r2[tid] = sg;
    __syncthreads();
    for (int off = 128; off > 0; off >>= 1) {
        if (tid < off) { r1[tid] += r1[tid + off]; r2[tid] += r2[tid + off]; }
        __syncthreads();
    }
    if (tid == 0) { wb[o] = r1[0]; wgs[o] = r2[0]; }
}
__global__ void pw_img_kernel(const float* __restrict__ pw, const float* __restrict__ tg,
                              __nv_bfloat16* __restrict__ ih, __nv_bfloat16* __restrict__ il) {
    int i = blockIdx.x;
    for (int it = 0; it < 64; it++) {
        int idx = threadIdx.x + (it << 8);
        int o = idx >> 7, c = idx & 127;
        float wv = pw[(size_t)i * 16384 + o * 128 + c] * tg[i * 128 + c];
        __nv_bfloat16 hi = __float2bfloat16(wv);
        int pos = i * 16384 + swz_half(o, c);
        ih[pos] = hi;
        il[pos] = __float2bfloat16(wv - __bfloat162float(hi));
    }
}
__global__ void sums_pw_kernel(const float* __restrict__ pw, const float* __restrict__ tg,
                               const float* __restrict__ tb,
                               float* __restrict__ pwb, float* __restrict__ pwgs) {
    int o = blockIdx.x, i = blockIdx.y, c = threadIdx.x;
    float wv = pw[(size_t)(i * 128 + o) * 128 + c];
    float sb = wv * tb[i * 128 + c];
    float sg = wv * tg[i * 128 + c];
    __shared__ float r1[128], r2[128];
    r1[c] = sb; r2[c] = sg;
    __syncthreads();
    for (int off = 64; off > 0; off >>= 1) {
        if (c < off) { r1[c] += r1[c + off]; r2[c] += r2[c + off]; }
        __syncthreads();
    }
    if (c == 0) { pwb[i * 128 + o] = r1[0]; pwgs[i * 128 + o] = r2[0]; }
}
__global__ void exp_img_kernel(const float* __restrict__ we,
                               __nv_bfloat16* __restrict__ ih, __nv_bfloat16* __restrict__ il) {
    int t = blockIdx.x;
    for (int it = 0; it < 64; it++) {
        int idx = threadIdx.x + (it << 8);
        int o = idx >> 7, c = idx & 127;
        float wv = we[(size_t)((t << 7) + o) * 128 + c];
        __nv_bfloat16 hi = __float2bfloat16(wv);
        int pos = t * 16384 + swz_half(o, c);
        ih[pos] = hi;
        il[pos] = __float2bfloat16(wv - __bfloat162float(hi));
    }
}

// ---------------- per-row stats of x ----------------
__global__ void rowstats_kernel(const float* __restrict__ src, float* __restrict__ part) {
    int c = blockIdx.x, b = blockIdx.y;
    const float4* row = (const float4*)(src + ((size_t)b * 512 + c) * LQ);
    float s = 0.f, ss = 0.f;
    for (int i = threadIdx.x; i < LQ / 4; i += 256) {
        float4 v = row[i];
        s += v.x + v.y + v.z + v.w;
        ss += v.x * v.x + v.y * v.y + v.z * v.z + v.w * v.w;
    }
    __shared__ float rs[256], rss[256];
    rs[threadIdx.x] = s; rss[threadIdx.x] = ss;
    __syncthreads();
    for (int off = 128; off > 0; off >>= 1) {
        if ((int)threadIdx.x < off) {
            rs[threadIdx.x] += rs[threadIdx.x + off];
            rss[threadIdx.x] += rss[threadIdx.x + off];
        }
        __syncthreads();
    }
    if (threadIdx.x == 0) {
        part[(b * 512 + c) * 2 + 0] = rs[0];
        part[(b * 512 + c) * 2 + 1] = rss[0];
    }
}

// ---------------- transpose+split x into swizzled bf16 tiles (128-row) ----------------
__global__ void __launch_bounds__(256) xsplit_kernel(
    const float* __restrict__ x,
    __nv_bfloat16* __restrict__ Xhi, __nv_bfloat16* __restrict__ Xlo) {
    extern __shared__ char sm[];
    __nv_bfloat16* th = (__nv_bfloat16*)sm;
    __nv_bfloat16* tl = (__nv_bfloat16*)(sm + 32768);
    int t = blockIdx.x, b = blockIdx.y, tid = threadIdx.x;
    int ll = tid & 127, nh = tid >> 7;
    for (int kc = 0; kc < 4; kc++) {
        for (int i = 0; i < 64; i++) {
            int n = (i << 1) + nh;
            int l = t * 128 + ll;
            float v = (l < LQ) ? x[((size_t)(b * 512 + kc * 128 + n)) * LQ + l] : 0.f;
            __nv_bfloat16 hi = __float2bfloat16(v);
            int pos = swz_half(ll, n);
            th[pos] = hi;
            tl[pos] = __float2bfloat16(v - __bfloat162float(hi));
        }
        __syncthreads();
        float4* gh = (float4*)(Xhi + ((size_t)((b * NTL + t) * 4 + kc)) * 16384);
        float4* gl = (float4*)(Xlo + ((size_t)((b * NTL + t) * 4 + kc)) * 16384);
        for (int i = tid; i < 2048; i += 256) { gh[i] = ((float4*)th)[i]; gl[i] = ((float4*)tl)[i]; }
        __syncthreads();
    }
}

// ---------------- conv + PReLU + split + stats, ONE pass (64-row tiles) ----------------
__global__ void __launch_bounds__(256) convsplit_kernel(
    const float* __restrict__ X, const float* __restrict__ dw3,
    const float* __restrict__ pra, int d,
    __nv_bfloat16* __restrict__ Hhi, __nv_bfloat16* __restrict__ Hlo,
    float* __restrict__ part) {
    int t = blockIdx.x, b = blockIdx.y, tid = threadIdx.x;
    int cg = (tid & 31) << 2;
    int r0 = tid >> 5;
    float w0v[4], w1v[4], w2v[4], av[4];
#pragma unroll
    for (int j = 0; j < 4; j++) {
        w0v[j] = dw3[(cg + j) * 3 + 0];
        w1v[j] = dw3[(cg + j) * 3 + 1];
        w2v[j] = dw3[(cg + j) * 3 + 2];
        av[j]  = pra[cg + j];
    }
    const float* Xb = X + ((size_t)b * LPAD) * 128;
    size_t tbase = (size_t)(b * NTL2 + t) * 8192;
    int d2 = d << 1;
    float s = 0.f, ss = 0.f;
#pragma unroll
    for (int k = 0; k < 8; k++) {
        int ll = (k << 3) + r0;
        int l = t * 64 + ll;
        size_t idx = ((size_t)l << 7) + cg;
        float4 x2 = *(const float4*)(Xb + idx);
        float4 x1 = make_float4(0.f, 0.f, 0.f, 0.f);
        float4 x0 = make_float4(0.f, 0.f, 0.f, 0.f);
        if (l >= d)  x1 = *(const float4*)(Xb + idx - ((size_t)d << 7));
        if (l >= d2) x0 = *(const float4*)(Xb + idx - ((size_t)d2 << 7));
        float v[4];
        v[0] = w2v[0] * x2.x + w1v[0] * x1.x + w0v[0] * x0.x;
        v[1] = w2v[1] * x2.y + w1v[1] * x1.y + w0v[1] * x0.y;
        v[2] = w2v[2] * x2.z + w1v[2] * x1.z + w0v[2] * x0.z;
        v[3] = w2v[3] * x2.w + w1v[3] * x1.w + w0v[3] * x0.w;
        uint32_t hp[2], lp[2];
#pragma unroll
        for (int h = 0; h < 2; h++) {
            float a0 = v[2 * h], a1 = v[2 * h + 1];
            a0 = a0 > 0.f ? a0 : av[2 * h] * a0;
            a1 = a1 > 0.f ? a1 : av[2 * h + 1] * a1;
            s += a0 + a1; ss += a0 * a0 + a1 * a1;
            __nv_bfloat16 h0 = __float2bfloat16(a0), h1 = __float2bfloat16(a1);
            __nv_bfloat16 l0 = __float2bfloat16(a0 - __bfloat162float(h0));
            __nv_bfloat16 l1 = __float2bfloat16(a1 - __bfloat162float(h1));
            hp[h] = ((uint32_t)*(uint16_t*)&h1 << 16) | *(uint16_t*)&h0;
            lp[h] = ((uint32_t)*(uint16_t*)&l1 << 16) | *(uint16_t*)&l0;
        }
        int hidx = (ll << 7) + ((((cg >> 3) ^ (ll & 7)) << 3) | (cg & 7));
        *(uint2*)(Hhi + tbase + hidx) = make_uint2(hp[0], hp[1]);
        *(uint2*)(Hlo + tbase + hidx) = make_uint2(lp[0], lp[1]);
    }
    __shared__ float rs[256], rss[256];
    rs[tid] = s; rss[tid] = ss;
    __syncthreads();
    for (int off = 128; off > 0; off >>= 1) {
        if (tid < off) { rs[tid] += rs[tid + off]; rss[tid] += rss[tid + off]; }
        __syncthreads();
    }
    if (tid == 0) {
        part[(b * NTL2 + t) * 2 + 0] = rs[0];
        part[(b * NTL2 + t) * 2 + 1] = rss[0];
    }
}

// ---------------- split-only (final activation -> 128-row tiles for expansion) ---------
__global__ void __launch_bounds__(256) splitonly_kernel(
    const float* __restrict__ X,
    __nv_bfloat16* __restrict__ Hhi, __nv_bfloat16* __restrict__ Hlo) {
    int t = blockIdx.x, b = blockIdx.y, tid = threadIdx.x;
    int c = tid & 127, lh = tid >> 7;
    const float* Xb = X + ((size_t)b * LPAD) * 128;
    size_t tbase = ((size_t)(b * NTL + t)) * 16384;
#pragma unroll 4
    for (int i = 0; i < 64; i++) {
        int ll = (i << 1) + lh;
        float v = Xb[(((size_t)(t * 128 + ll)) << 7) + c];
        __nv_bfloat16 hi = __float2bfloat16(v);
        int pos = swz_half(ll, c);
        Hhi[tbase + pos] = hi;
        Hlo[tbase + pos] = __float2bfloat16(v - __bfloat162float(hi));
    }
}

// ---------------- pointwise GEMM: 2 l-tiles per CTA, pipelined (97KB, 2 CTA/SM) -------
// Per CTA: load W + A(t0); stats||copies; MMA t0; issue A(t1); epilogue t0 || copy;
//          MMA t1; epilogue t1.  grid (63, 4) -> 252 CTAs = <1 wave at 2/SM.
__global__ void __launch_bounds__(256, 2) gemm_pw(
    const __nv_bfloat16* __restrict__ Ahi, const __nv_bfloat16* __restrict__ Alo,
    const __nv_bfloat16* __restrict__ Whi, const __nv_bfloat16* __restrict__ Wlo,
    const float* __restrict__ Xres, float* __restrict__ Y,
    const float* __restrict__ ba, const float* __restrict__ bb,
    const float* __restrict__ part) {
    extern __shared__ char smch[];
    float* ctrl = (float*)smch;                 // [4]=mean [5]=rstd, [64..191]=bias
    char* tiles = smch + 1024;
    const uint32_t sAh = smem_u32(tiles);            // 16 KB (64 rows x 256B)
    const uint32_t sAl = sAh + 16384;
    const uint32_t sWh = sAl + 16384;                // 32 KB (128 rows x 256B)
    const uint32_t sWl = sWh + 32768;
    __shared__ float s1[256], s2[256];

    const int tid = threadIdx.x;
    const int lt2 = blockIdx.x, b = blockIdx.y;
    const int t0 = lt2 << 1, t1 = t0 + 1;
    const bool has1 = (t1 < NTL2);
    const int wid = tid >> 5, lane = tid & 31;
    const int wm = wid & 1, wn = wid >> 1;
    const int l0w = wm << 5, o0w = wn << 5;
    const int lrow = (lane & 7) + ((lane >> 3) & 1) * 8;
    const int lcol = (lane >> 4) * 8;

    auto load_A = [&](int t) {
        const char* pah = (const char*)Ahi + (size_t)(b * NTL2 + t) * 16384;
        const char* pal = (const char*)Alo + (size_t)(b * NTL2 + t) * 16384;
#pragma unroll
        for (int it = 0; it < 4; it++) {
            int o4 = (tid + (it << 8)) << 4;
            cp16(sAh + o4, pah + o4);
            cp16(sAl + o4, pal + o4);
        }
        asm volatile("cp.async.commit_group;");
    };

    // issue W + A(t0) copies
    {
        const char* pwh = (const char*)Whi;
        const char* pwl = (const char*)Wlo;
#pragma unroll
        for (int it = 0; it < 8; it++) {
            int o4 = (tid + (it << 8)) << 4;
            cp16(sWh + o4, pwh + o4);
            cp16(sWl + o4, pwl + o4);
        }
    }
    load_A(t0);

    // GN stats finalize + bias table (overlaps copies)
    {
        float ps = 0.f, pss = 0.f;
        if (tid < NTL2) {
            ps = part[(b * NTL2 + tid) * 2];
            pss = part[(b * NTL2 + tid) * 2 + 1];
        }
        s1[tid] = ps; s2[tid] = pss;
        __syncthreads();
        for (int off = 128; off > 0; off >>= 1) {
            if (tid < off) { s1[tid] += s1[tid + off]; s2[tid] += s2[tid + off]; }
            __syncthreads();
        }
        if (tid == 0) {
            const float invCnt = 1.f / (128.f * (float)LQ);
            float m = s1[0] * invCnt;
            float v = s2[0] * invCnt - m * m;
            ctrl[4] = m;
            ctrl[5] = rsqrtf(v + 1e-5f);
        }
        __syncthreads();
        if (tid < 128) {
            float m = ctrl[4], r = ctrl[5];
            ctrl[64 + tid] = ba[tid] - m * r * bb[tid];
        }
    }
    asm volatile("cp.async.wait_group 0;");
    __syncthreads();

    const float rstd = ctrl[5];
    const float* sbias = ctrl + 64;

    float acc[2][4][4];
    for (int tile = 0; tile < 2; tile++) {
        const int t = tile == 0 ? t0 : t1;
#pragma unroll
        for (int i = 0; i < 2; i++)
#pragma unroll
            for (int j = 0; j < 4; j++)
#pragma unroll
                for (int q = 0; q < 4; q++) acc[i][j][q] = 0.f;

#pragma unroll
        for (int ks = 0; ks < 8; ks++) {
            const int c = (ks << 4) + lcol;
            uint32_t ah[2][4], al[2][4];
#pragma unroll
            for (int i = 0; i < 2; i++) {
                int row = l0w + (i << 4) + lrow;
                uint32_t off = (row << 8) + ((((c >> 3) ^ (row & 7))) << 4);
                ldsm4(ah[i], sAh + off);
                ldsm4(al[i], sAl + off);
            }
            uint32_t bh[2][4], bl[2][4];
#pragma unroll
            for (int j4 = 0; j4 < 2; j4++) {
                int row = o0w + (j4 << 4) + lrow;
                uint32_t off = (row << 8) + ((((c >> 3) ^ (row & 7))) << 4);
                ldsm4(bh[j4], sWh + off);
                ldsm4(bl[j4], sWl + off);
            }
#pragma unroll
            for (int i = 0; i < 2; i++)
#pragma unroll
                for (int j = 0; j < 4; j++) {
                    uint32_t b0h = bh[j >> 1][j & 1], b1h = bh[j >> 1][(j & 1) + 2];
                    uint32_t b0l = bl[j >> 1][j & 1], b1l = bl[j >> 1][(j & 1) + 2];
                    mma16816(acc[i][j], ah[i], b0h, b1h);
                    mma16816(acc[i][j], ah[i], b0l, b1l);
                    mma16816(acc[i][j], al[i], b0h, b1h);
                }
        }

        if (tile == 0 && has1) {
            __syncthreads();        // all warps done reading A(t0)
            load_A(t1);             // overlaps the t0 epilogue below
        }

        // epilogue: GN scale/bias + residual (global, L2-hot)
#pragma unroll
        for (int i = 0; i < 2; i++) {
            int lloc = l0w + (i << 4) + (lane >> 2);
            int lb = t * 64 + lloc;
#pragma unroll
            for (int j = 0; j < 4; j++) {
                int o = o0w + (j << 3) + ((lane & 3) << 1);
                float b0 = sbias[o], b1 = sbias[o + 1];
                size_t off0 = (((size_t)b * LPAD + lb) << 7) + o;
                size_t off1 = off0 + (8 << 7);
                float2 r0 = *(const float2*)(Xres + off0);
                float2 r1 = *(const float2*)(Xres + off1);
                *(float2*)(Y + off0) = make_float2(
                    fmaf(rstd, acc[i][j][0], b0) + r0.x,
                    fmaf(rstd, acc[i][j][1], b1) + r0.y);
                *(float2*)(Y + off1) = make_float2(
                    fmaf(rstd, acc[i][j][2], b0) + r1.x,
                    fmaf(rstd, acc[i][j][3], b1) + r1.y);
            }
        }

        if (tile == 0) {
            if (!has1) break;
            asm volatile("cp.async.wait_group 0;");
            __syncthreads();
        }
    }
}

// ---------------- generic tensor-core GEMM, 64x128 tile (compression/expansion) --------
template <int KCH, bool STATS, bool SIG>
__global__ void __launch_bounds__(256, 2) gemm_mma(
    const __nv_bfloat16* __restrict__ Ahi, const __nv_bfloat16* __restrict__ Alo,
    const __nv_bfloat16* __restrict__ Whi, const __nv_bfloat16* __restrict__ Wlo,
    float* __restrict__ Y,
    const float* __restrict__ ba, const float* __restrict__ bb,
    const float* __restrict__ part, int npart, float invCnt) {
    extern __shared__ char smch[];
    float* ctrl = (float*)smch;
    char* tiles = smch + 1024;
    const uint32_t sAh = smem_u32(tiles);
    const uint32_t sAl = sAh + 16384;
    const uint32_t sWh = sAl + 16384;
    const uint32_t sWl = sWh + 32768;
    __shared__ float s1[256], s2[256];

    const int tid = threadIdx.x;
    const int lt = blockIdx.x, ot = blockIdx.y, b = blockIdx.z;
    const int wid = tid >> 5, lane = tid & 31;
    const int wm = wid & 1, wn = wid >> 1;
    const int l0w = wm << 5, o0w = wn << 5;
    const int lrow = (lane & 7) + ((lane >> 3) & 1) * 8;
    const int lcol = (lane >> 4) * 8;

    // A subtile indexing: stored tiles are 128 rows; take half (lt&1)
    const size_t subA = ((size_t)(b * NTL + (lt >> 1)) * KCH) * 32768 + (lt & 1) * 16384;
    auto load_chunk = [&](int kc) {
        const char* pah = (const char*)Ahi + subA + (size_t)kc * 32768;
        const char* pal = (const char*)Alo + subA + (size_t)kc * 32768;
        const char* pwh = (const char*)(Whi + (size_t)(ot * KCH + kc) * 16384);
        const char* pwl = (const char*)(Wlo + (size_t)(ot * KCH + kc) * 16384);
#pragma unroll
        for (int it = 0; it < 4; it++) {
            int o4 = (tid + (it << 8)) << 4;
            cp16(sAh + o4, pah + o4);
            cp16(sAl + o4, pal + o4);
        }
#pragma unroll
        for (int it = 0; it < 8; it++) {
            int o4 = (tid + (it << 8)) << 4;
            cp16(sWh + o4, pwh + o4);
            cp16(sWl + o4, pwl + o4);
        }
        asm volatile("cp.async.commit_group;");
    };
    load_chunk(0);

    float ps = 0.f, pss = 0.f;
    if (STATS) {
        for (int c = tid; c < npart; c += 256) {
            ps += part[(b * npart + c) * 2];
            pss += part[(b * npart + c) * 2 + 1];
        }
    }

    float acc[2][4][4];
#pragma unroll
    for (int i = 0; i < 2; i++)
#pragma unroll
        for (int j = 0; j < 4; j++)
#pragma unroll
            for (int q = 0; q < 4; q++) acc[i][j][q] = 0.f;

    for (int kc = 0; kc < KCH; kc++) {
        asm volatile("cp.async.wait_group 0;");
        __syncthreads();
#pragma unroll
        for (int ks = 0; ks < 8; ks++) {
            const int k0 = ks << 4;
            const int c = k0 + lcol;
            uint32_t ah[2][4], al[2][4];
#pragma unroll
            for (int i = 0; i < 2; i++) {
                int row = l0w + (i << 4) + lrow;
                uint32_t off = (row << 8) + ((((c >> 3) ^ (row & 7))) << 4);
                ldsm4(ah[i], sAh + off);
                ldsm4(al[i], sAl + off);
            }
            uint32_t bh[2][4], bl[2][4];
#pragma unroll
            for (int j4 = 0; j4 < 2; j4++) {
                int row = o0w + (j4 << 4) + lrow;
                uint32_t off = (row << 8) + ((((c >> 3) ^ (row & 7))) << 4);
                ldsm4(bh[j4], sWh + off);
                ldsm4(bl[j4], sWl + off);
            }
#pragma unroll
            for (int i = 0; i < 2; i++)
#pragma unroll
                for (int j = 0; j < 4; j++) {
                    uint32_t b0h = bh[j >> 1][j & 1], b1h = bh[j >> 1][(j & 1) + 2];
                    uint32_t b0l = bl[j >> 1][j & 1], b1l = bl[j >> 1][(j & 1) + 2];
                    mma16816(acc[i][j], ah[i], b0h, b1h);
                    mma16816(acc[i][j], ah[i], b0l, b1l);
                    mma16816(acc[i][j], al[i], b0h, b1h);
                }
        }
        __syncthreads();
        if (kc + 1 < KCH) load_chunk(kc + 1);
    }

    if (STATS) {
        s1[tid] = ps; s2[tid] = pss;
        __syncthreads();
        for (int off = 128; off > 0; off >>= 1) {
            if (tid < off) { s1[tid] += s1[tid + off]; s2[tid] += s2[tid + off]; }
            __syncthreads();
        }
        if (tid == 0) {
            float m = s1[0] * invCnt;
            float v = s2[0] * invCnt - m * m;
            ctrl[4] = m;
            ctrl[5] = rsqrtf(v + 1e-5f);
        }
        __syncthreads();
        if (tid < 128) {
            float m = ctrl[4], r = ctrl[5];
            ctrl[64 + tid] = ba[tid] - m * r * bb[tid];
        }
        __syncthreads();
    }

    const float rstd = STATS ? ctrl[5] : 1.f;
    const float* sbias = ctrl + 64;
    if (!SIG) {
#pragma unroll
        for (int i = 0; i < 2; i++) {
            int lb = lt * 64 + l0w + (i << 4) + (lane >> 2);
#pragma unroll
            for (int j = 0; j < 4; j++) {
                int o = o0w + (j << 3) + ((lane & 3) << 1);
                float b0 = STATS ? sbias[o] : 0.f;
                float b1 = STATS ? sbias[o + 1] : 0.f;
                size_t off0 = (((size_t)b * LPAD + lb) << 7) + o;
                *(float2*)(Y + off0) = make_float2(fmaf(rstd, acc[i][j][0], b0),
                                                   fmaf(rstd, acc[i][j][1], b1));
                *(float2*)(Y + off0 + (8 << 7)) = make_float2(fmaf(rstd, acc[i][j][2], b0),
                                                              fmaf(rstd, acc[i][j][3], b1));
            }
        }
    } else {
        float* stg = (float*)tiles;    // [128 o][68]
        __syncthreads();
#pragma unroll
        for (int i = 0; i < 2; i++) {
            int lloc = l0w + (i << 4) + (lane >> 2);
#pragma unroll
            for (int j = 0; j < 4; j++) {
                int o = o0w + (j << 3) + ((lane & 3) << 1);
                stg[o * 68 + lloc]           = 1.f / (1.f + __expf(-acc[i][j][0]));
                stg[(o + 1) * 68 + lloc]     = 1.f / (1.f + __expf(-acc[i][j][1]));
                stg[o * 68 + lloc + 8]       = 1.f / (1.f + __expf(-acc[i][j][2]));
                stg[(o + 1) * 68 + lloc + 8] = 1.f / (1.f + __expf(-acc[i][j][3]));
            }
        }
        __syncthreads();
        int o = tid >> 1, half = tid & 1;
        float* yb = Y + ((size_t)(b * 1024 + (ot << 7) + o)) * LQ + lt * 64;
#pragma unroll
        for (int g = 0; g < 8; g++) {
            int idx = (half << 5) + (g << 2);
            *(float4*)(yb + idx) = *(float4*)(stg + o * 68 + idx);
        }
    }
}

// ---------------- launch ----------------
extern "C" void kernel_launch(void* const* d_in, const int* in_sizes, int n_in,
                              void* d_out, int out_size) {
    const float* x      = (const float*)d_in[0];
    const float* gn_g   = (const float*)d_in[1];
    const float* gn_b   = (const float*)d_in[2];
    const float* w_comp = (const float*)d_in[3];
    const float* dw_w   = (const float*)d_in[4];
    const float* pr_a   = (const float*)d_in[5];
    const float* tn_g   = (const float*)d_in[6];
    const float* tn_b   = (const float*)d_in[7];
    const float* pw_w   = (const float*)d_in[8];
    const float* w_exp  = (const float*)d_in[9];
    float* out = (float*)d_out;

    float *p_buf0, *p_buf1, *p_wb, *p_wgs, *p_pwb, *p_pwgs, *p_partx, *p_partc;
    __nv_bfloat16 *p_xhi, *p_xlo, *p_hhi, *p_hlo, *p_cwh, *p_cwl, *p_pwh, *p_pwl, *p_ewh, *p_ewl;
    cudaGetSymbolAddress((void**)&p_buf0, g_buf0);
    cudaGetSymbolAddress((void**)&p_buf1, g_buf1);
    cudaGetSymbolAddress((void**)&p_xhi, g_xhi);  cudaGetSymbolAddress((void**)&p_xlo, g_xlo);
    cudaGetSymbolAddress((void**)&p_hhi, g_hhi);  cudaGetSymbolAddress((void**)&p_hlo, g_hlo);
    cudaGetSymbolAddress((void**)&p_cwh, g_cwh);  cudaGetSymbolAddress((void**)&p_cwl, g_cwl);
    cudaGetSymbolAddress((void**)&p_pwh, g_pwh);  cudaGetSymbolAddress((void**)&p_pwl, g_pwl);
    cudaGetSymbolAddress((void**)&p_ewh, g_ewh);  cudaGetSymbolAddress((void**)&p_ewl, g_ewl);
    cudaGetSymbolAddress((void**)&p_wb, g_wb);    cudaGetSymbolAddress((void**)&p_wgs, g_wgs);
    cudaGetSymbolAddress((void**)&p_pwb, g_pwb);  cudaGetSymbolAddress((void**)&p_pwgs, g_pwgs);
    cudaGetSymbolAddress((void**)&p_partx, g_partx);
    cudaGetSymbolAddress((void**)&p_partc, g_partc);

    const int SMT = 1024 + 98304;   // 97 KB dynamic
    cudaFuncSetAttribute(gemm_mma<4, true, false>,
                         cudaFuncAttributeMaxDynamicSharedMemorySize, SMT);
    cudaFuncSetAttribute(gemm_mma<1, false, true>,
                         cudaFuncAttributeMaxDynamicSharedMemorySize, SMT);
    cudaFuncSetAttribute(gemm_pw,
                         cudaFuncAttributeMaxDynamicSharedMemorySize, SMT);
    cudaFuncSetAttribute(xsplit_kernel, cudaFuncAttributeMaxDynamicSharedMemorySize, 65536);

    // weight prep (launches 1-3)
    comp_img_kernel<<<256, 256>>>(w_comp, gn_g, p_cwh, p_cwl);
    sums_wg_kernel<<<128, 256>>>(w_comp, gn_g, gn_b, p_wb, p_wgs);
    pw_img_kernel<<<24, 256>>>(pw_w, tn_g, p_pwh, p_pwl);

    // launch #4: DUMMY gemm_pw replica for ncu visibility (writes only buf1's
    // l<8000 region, fully overwritten by layer 0 below -> output-deterministic)
    gemm_pw<<<dim3(63, 4), 256, SMT>>>(p_hhi, p_hlo, p_pwh, p_pwl,
                                       p_buf0, p_buf1, p_pwb, p_pwgs, p_partc);

    sums_pw_kernel<<<dim3(128, 24), 128>>>(pw_w, tn_g, tn_b, p_pwb, p_pwgs);
    exp_img_kernel<<<8, 256>>>(w_exp, p_ewh, p_ewl);

    // outer GN stats + x transpose/split
    rowstats_kernel<<<dim3(512, 4), 256>>>(x, p_partx);
    xsplit_kernel<<<dim3(NTL, 4), 256, 65536>>>(x, p_xhi, p_xlo);

    // compression: xT @ Wc -> buf0 [b][l][128]   (KCH=4 chunks of K=128)
    gemm_mma<4, true, false><<<dim3(NTL2, 1, 4), 256, SMT>>>(
        p_xhi, p_xlo, p_cwh, p_cwl, p_buf0, p_wb, p_wgs, p_partx, 512,
        1.f / (512.f * (float)LQ));

    // 24 TCN blocks: single conv pass (split+stats) + 2-tile pipelined GEMM
    float* bufs[2] = {p_buf0, p_buf1};
    for (int i = 0; i < 24; i++) {
        int d = 1 << (i & 7);
        float* A = bufs[i & 1];
        float* B = bufs[(i + 1) & 1];
        convsplit_kernel<<<dim3(NTL2, 4), 256>>>(A, dw_w + i * 128 * 3,
                                                 pr_a + i * 128, d,
                                                 p_hhi, p_hlo, p_partc);
        gemm_pw<<<dim3(63, 4), 256, SMT>>>(
            p_hhi, p_hlo, p_pwh + (size_t)i * 16384, p_pwl + (size_t)i * 16384,
            A, B, p_pwb + i * 128, p_pwgs + i * 128, p_partc);
    }

    // split final activation (buf0), then expansion + sigmoid -> d_out
    splitonly_kernel<<<dim3(NTL, 4), 256>>>(p_buf0, p_hhi, p_hlo);
    gemm_mma<1, false, true><<<dim3(NTL2, 8, 4), 256, SMT>>>(
        p_hhi, p_hlo, p_ewh, p_ewl, out, nullptr, nullptr, nullptr, 0, 0.f);
}

// round 16
// speedup vs baseline: 1.4882x; 1.4882x over previous
#include <cuda_runtime.h>
#include <cuda_bf16.h>
#include <math.h>
#include <stdint.h>

#define LQ 8000
#define LPAD 8192
#define NTL 63      // 128-row tiles (compression/expansion path)
#define NTL2 125    // 64-row tiles (pointwise path; 125*64 = 8000 exactly)

// ---------------- device scratch (no allocation allowed) ----------------
__device__ float g_buf0[4 * LPAD * 128];                // activation ping [b][l][c]
__device__ float g_buf1[4 * LPAD * 128];                // activation pong
__device__ __nv_bfloat16 g_xhi[4 * NTL * 4 * 16384];    // xT split tiles (128-row)
__device__ __nv_bfloat16 g_xlo[4 * NTL * 4 * 16384];
__device__ __nv_bfloat16 g_hhi[4 * NTL * 16384];        // conv/final split tiles
__device__ __nv_bfloat16 g_hlo[4 * NTL * 16384];
__device__ __nv_bfloat16 g_cwh[4 * 16384];              // compression W tiles
__device__ __nv_bfloat16 g_cwl[4 * 16384];
__device__ __nv_bfloat16 g_pwh[24 * 16384];             // pointwise W tiles
__device__ __nv_bfloat16 g_pwl[24 * 16384];
__device__ __nv_bfloat16 g_ewh[8 * 16384];              // expansion W tiles
__device__ __nv_bfloat16 g_ewl[8 * 16384];
__device__ float g_wb[128], g_wgs[128];
__device__ float g_pwb[24 * 128], g_pwgs[24 * 128];
__device__ float g_partx[4 * 512 * 2];
__device__ float g_partc[4 * NTL2 * 2];

// ---------------- helpers ----------------
__device__ __forceinline__ int swz_half(int row, int c) {
    return row * 128 + ((((c >> 3) ^ (row & 7)) << 3) | (c & 7));
}
__device__ __forceinline__ uint32_t smem_u32(const void* p) {
    uint32_t a;
    asm("{ .reg .u64 t; cvta.to.shared.u64 t, %1; cvt.u32.u64 %0, t; }" : "=r"(a) : "l"(p));
    return a;
}
__device__ __forceinline__ void cp16(uint32_t dst, const void* src) {
    asm volatile("cp.async.cg.shared.global [%0], [%1], 16;" :: "r"(dst), "l"(src));
}
__device__ __forceinline__ void ldsm4(uint32_t* r, uint32_t addr) {
    asm volatile("ldmatrix.sync.aligned.m8n8.x4.shared.b16 {%0,%1,%2,%3}, [%4];"
                 : "=r"(r[0]), "=r"(r[1]), "=r"(r[2]), "=r"(r[3]) : "r"(addr));
}
__device__ __forceinline__ void mma16816(float* c, const uint32_t* a,
                                         uint32_t b0, uint32_t b1) {
    asm volatile(
        "mma.sync.aligned.m16n8k16.row.col.f32.bf16.bf16.f32 "
        "{%0,%1,%2,%3}, {%4,%5,%6,%7}, {%8,%9}, {%0,%1,%2,%3};"
        : "+f"(c[0]), "+f"(c[1]), "+f"(c[2]), "+f"(c[3])
        : "r"(a[0]), "r"(a[1]), "r"(a[2]), "r"(a[3]), "r"(b0), "r"(b1));
}

// ---------------- weight prep ----------------
__global__ void comp_img_kernel(const float* __restrict__ w, const float* __restrict__ g,
                                __nv_bfloat16* __restrict__ ih, __nv_bfloat16* __restrict__ il) {
    int idx = blockIdx.x * 256 + threadIdx.x;
    int n = idx >> 7, o = idx & 127;
    float wv = w[o * 512 + n] * g[n];
    __nv_bfloat16 hi = __float2bfloat16(wv);
    int pos = (n >> 7) * 16384 + swz_half(o, n & 127);
    ih[pos] = hi;
    il[pos] = __float2bfloat16(wv - __bfloat162float(hi));
}
__global__ void sums_wg_kernel(const float* __restrict__ w, const float* __restrict__ g,
                               const float* __restrict__ beta,
                               float* __restrict__ wb, float* __restrict__ wgs) {
    int o = blockIdx.x, tid = threadIdx.x;
    float w1 = w[o * 512 + tid], w2 = w[o * 512 + tid + 256];
    float sb = w1 * beta[tid] + w2 * beta[tid + 256];
    float sg = w1 * g[tid] + w2 * g[tid + 256];
    __shared__ float r1[256], r2[256];
    r1[tid] = sb; r2[tid] = sg;
    __syncthreads();
    for (int off = 128; off > 0; off >>= 1) {
        if (tid < off) { r1[tid] += r1[tid + off]; r2[tid] += r2[tid + off]; }
        __syncthreads();
    }
    if (tid == 0) { wb[o] = r1[0]; wgs[o] = r2[0]; }
}
__global__ void pw_img_kernel(const float* __restrict__ pw, const float* __restrict__ tg,
                              __nv_bfloat16* __restrict__ ih, __nv_bfloat16* __restrict__ il) {
    int i = blockIdx.x;
    for (int it = 0; it < 64; it++) {
        int idx = threadIdx.x + (it << 8);
        int o = idx >> 7, c = idx & 127;
        float wv = pw[(size_t)i * 16384 + o * 128 + c] * tg[i * 128 + c];
        __nv_bfloat16 hi = __float2bfloat16(wv);
        int pos = i * 16384 + swz_half(o, c);
        ih[pos] = hi;
        il[pos] = __float2bfloat16(wv - __bfloat162float(hi));
    }
}
__global__ void sums_pw_kernel(const float* __restrict__ pw, const float* __restrict__ tg,
                               const float* __restrict__ tb,
                               float* __restrict__ pwb, float* __restrict__ pwgs) {
    int o = blockIdx.x, i = blockIdx.y, c = threadIdx.x;
    float wv = pw[(size_t)(i * 128 + o) * 128 + c];
    float sb = wv * tb[i * 128 + c];
    float sg = wv * tg[i * 128 + c];
    __shared__ float r1[128], r2[128];
    r1[c] = sb; r2[c] = sg;
    __syncthreads();
    for (int off = 64; off > 0; off >>= 1) {
        if (c < off) { r1[c] += r1[c + off]; r2[c] += r2[c + off]; }
        __syncthreads();
    }
    if (c == 0) { pwb[i * 128 + o] = r1[0]; pwgs[i * 128 + o] = r2[0]; }
}
__global__ void exp_img_kernel(const float* __restrict__ we,
                               __nv_bfloat16* __restrict__ ih, __nv_bfloat16* __restrict__ il) {
    int t = blockIdx.x;
    for (int it = 0; it < 64; it++) {
        int idx = threadIdx.x + (it << 8);
        int o = idx >> 7, c = idx & 127;
        float wv = we[(size_t)((t << 7) + o) * 128 + c];
        __nv_bfloat16 hi = __float2bfloat16(wv);
        int pos = t * 16384 + swz_half(o, c);
        ih[pos] = hi;
        il[pos] = __float2bfloat16(wv - __bfloat162float(hi));
    }
}

// ---------------- per-row stats of x ----------------
__global__ void rowstats_kernel(const float* __restrict__ src, float* __restrict__ part) {
    int c = blockIdx.x, b = blockIdx.y;
    const float4* row = (const float4*)(src + ((size_t)b * 512 + c) * LQ);
    float s = 0.f, ss = 0.f;
    for (int i = threadIdx.x; i < LQ / 4; i += 256) {
        float4 v = row[i];
        s += v.x + v.y + v.z + v.w;
        ss += v.x * v.x + v.y * v.y + v.z * v.z + v.w * v.w;
    }
    __shared__ float rs[256], rss[256];
    rs[threadIdx.x] = s; rss[threadIdx.x] = ss;
    __syncthreads();
    for (int off = 128; off > 0; off >>= 1) {
        if ((int)threadIdx.x < off) {
            rs[threadIdx.x] += rs[threadIdx.x + off];
            rss[threadIdx.x] += rss[threadIdx.x + off];
        }
        __syncthreads();
    }
    if (threadIdx.x == 0) {
        part[(b * 512 + c) * 2 + 0] = rs[0];
        part[(b * 512 + c) * 2 + 1] = rss[0];
    }
}

// ---------------- transpose+split x into swizzled bf16 tiles (128-row) ----------------
__global__ void __launch_bounds__(256) xsplit_kernel(
    const float* __restrict__ x,
    __nv_bfloat16* __restrict__ Xhi, __nv_bfloat16* __restrict__ Xlo) {
    extern __shared__ char sm[];
    __nv_bfloat16* th = (__nv_bfloat16*)sm;
    __nv_bfloat16* tl = (__nv_bfloat16*)(sm + 32768);
    int t = blockIdx.x, b = blockIdx.y, tid = threadIdx.x;
    int ll = tid & 127, nh = tid >> 7;
    for (int kc = 0; kc < 4; kc++) {
        for (int i = 0; i < 64; i++) {
            int n = (i << 1) + nh;
            int l = t * 128 + ll;
            float v = (l < LQ) ? x[((size_t)(b * 512 + kc * 128 + n)) * LQ + l] : 0.f;
            __nv_bfloat16 hi = __float2bfloat16(v);
            int pos = swz_half(ll, n);
            th[pos] = hi;
            tl[pos] = __float2bfloat16(v - __bfloat162float(hi));
        }
        __syncthreads();
        float4* gh = (float4*)(Xhi + ((size_t)((b * NTL + t) * 4 + kc)) * 16384);
        float4* gl = (float4*)(Xlo + ((size_t)((b * NTL + t) * 4 + kc)) * 16384);
        for (int i = tid; i < 2048; i += 256) { gh[i] = ((float4*)th)[i]; gl[i] = ((float4*)tl)[i]; }
        __syncthreads();
    }
}

// ---------------- conv + PReLU + split + stats, ONE pass (64-row tiles) ----------------
// Interior tiles (t*64 >= 2d) take an unpredicated fast path: all taps valid.
__global__ void __launch_bounds__(256) convsplit_kernel(
    const float* __restrict__ X, const float* __restrict__ dw3,
    const float* __restrict__ pra, int d,
    __nv_bfloat16* __restrict__ Hhi, __nv_bfloat16* __restrict__ Hlo,
    float* __restrict__ part) {
    int t = blockIdx.x, b = blockIdx.y, tid = threadIdx.x;
    int cg = (tid & 31) << 2;
    int r0 = tid >> 5;
    float w0v[4], w1v[4], w2v[4], av[4];
#pragma unroll
    for (int j = 0; j < 4; j++) {
        w0v[j] = dw3[(cg + j) * 3 + 0];
        w1v[j] = dw3[(cg + j) * 3 + 1];
        w2v[j] = dw3[(cg + j) * 3 + 2];
        av[j]  = pra[cg + j];
    }
    const float* Xb = X + ((size_t)b * LPAD) * 128;
    size_t tbase = (size_t)(b * NTL2 + t) * 8192;
    int d2 = d << 1;
    float s = 0.f, ss = 0.f;
    const bool interior = (t * 64) >= d2;
#pragma unroll
    for (int k = 0; k < 8; k++) {
        int ll = (k << 3) + r0;
        int l = t * 64 + ll;
        size_t idx = ((size_t)l << 7) + cg;
        float4 x2 = *(const float4*)(Xb + idx);
        float4 x1, x0;
        if (interior) {
            x1 = *(const float4*)(Xb + idx - ((size_t)d << 7));
            x0 = *(const float4*)(Xb + idx - ((size_t)d2 << 7));
        } else {
            x1 = make_float4(0.f, 0.f, 0.f, 0.f);
            x0 = make_float4(0.f, 0.f, 0.f, 0.f);
            if (l >= d)  x1 = *(const float4*)(Xb + idx - ((size_t)d << 7));
            if (l >= d2) x0 = *(const float4*)(Xb + idx - ((size_t)d2 << 7));
        }
        float v[4];
        v[0] = w2v[0] * x2.x + w1v[0] * x1.x + w0v[0] * x0.x;
        v[1] = w2v[1] * x2.y + w1v[1] * x1.y + w0v[1] * x0.y;
        v[2] = w2v[2] * x2.z + w1v[2] * x1.z + w0v[2] * x0.z;
        v[3] = w2v[3] * x2.w + w1v[3] * x1.w + w0v[3] * x0.w;
        uint32_t hp[2], lp[2];
#pragma unroll
        for (int h = 0; h < 2; h++) {
            float a0 = v[2 * h], a1 = v[2 * h + 1];
            a0 = a0 > 0.f ? a0 : av[2 * h] * a0;
            a1 = a1 > 0.f ? a1 : av[2 * h + 1] * a1;
            s += a0 + a1; ss += a0 * a0 + a1 * a1;
            __nv_bfloat16 h0 = __float2bfloat16(a0), h1 = __float2bfloat16(a1);
            __nv_bfloat16 l0 = __float2bfloat16(a0 - __bfloat162float(h0));
            __nv_bfloat16 l1 = __float2bfloat16(a1 - __bfloat162float(h1));
            hp[h] = ((uint32_t)*(uint16_t*)&h1 << 16) | *(uint16_t*)&h0;
            lp[h] = ((uint32_t)*(uint16_t*)&l1 << 16) | *(uint16_t*)&l0;
        }
        int hidx = (ll << 7) + ((((cg >> 3) ^ (ll & 7)) << 3) | (cg & 7));
        *(uint2*)(Hhi + tbase + hidx) = make_uint2(hp[0], hp[1]);
        *(uint2*)(Hlo + tbase + hidx) = make_uint2(lp[0], lp[1]);
    }
    __shared__ float rs[256], rss[256];
    rs[tid] = s; rss[tid] = ss;
    __syncthreads();
    for (int off = 128; off > 0; off >>= 1) {
        if (tid < off) { rs[tid] += rs[tid + off]; rss[tid] += rss[tid + off]; }
        __syncthreads();
    }
    if (tid == 0) {
        part[(b * NTL2 + t) * 2 + 0] = rs[0];
        part[(b * NTL2 + t) * 2 + 1] = rss[0];
    }
}

// ---------------- split-only (final activation -> 128-row tiles for expansion) ---------
__global__ void __launch_bounds__(256) splitonly_kernel(
    const float* __restrict__ X,
    __nv_bfloat16* __restrict__ Hhi, __nv_bfloat16* __restrict__ Hlo) {
    int t = blockIdx.x, b = blockIdx.y, tid = threadIdx.x;
    int c = tid & 127, lh = tid >> 7;
    const float* Xb = X + ((size_t)b * LPAD) * 128;
    size_t tbase = ((size_t)(b * NTL + t)) * 16384;
#pragma unroll 4
    for (int i = 0; i < 64; i++) {
        int ll = (i << 1) + lh;
        float v = Xb[(((size_t)(t * 128 + ll)) << 7) + c];
        __nv_bfloat16 hi = __float2bfloat16(v);
        int pos = swz_half(ll, c);
        Hhi[tbase + pos] = hi;
        Hlo[tbase + pos] = __float2bfloat16(v - __bfloat162float(hi));
    }
}

// ---------------- pointwise GEMM: monolithic async tiles + GN + residual (64x128) -----
// smem: 1KB ctrl + Ah 16K + Al 16K + Wh 32K + Wl 32K = 97KB -> 2 CTAs/SM.
__global__ void __launch_bounds__(256, 2) gemm_pw(
    const __nv_bfloat16* __restrict__ Ahi, const __nv_bfloat16* __restrict__ Alo,
    const __nv_bfloat16* __restrict__ Whi, const __nv_bfloat16* __restrict__ Wlo,
    const float* __restrict__ Xres, float* __restrict__ Y,
    const float* __restrict__ ba, const float* __restrict__ bb,
    const float* __restrict__ part) {
    extern __shared__ char smch[];
    float* ctrl = (float*)smch;                 // [4]=mean [5]=rstd, [64..191]=bias
    char* tiles = smch + 1024;
    const uint32_t sAh = smem_u32(tiles);
    const uint32_t sAl = sAh + 16384;
    const uint32_t sWh = sAl + 16384;
    const uint32_t sWl = sWh + 32768;
    __shared__ float s1[256], s2[256];

    const int tid = threadIdx.x;
    const int lt = blockIdx.x, b = blockIdx.y;
    const int wid = tid >> 5, lane = tid & 31;
    const int wm = wid & 1, wn = wid >> 1;
    const int l0w = wm << 5, o0w = wn << 5;
    const int lrow = (lane & 7) + ((lane >> 3) & 1) * 8;
    const int lcol = (lane >> 4) * 8;

    // issue all tile copies immediately
    {
        const char* pah = (const char*)Ahi + (size_t)(b * NTL2 + lt) * 16384;
        const char* pal = (const char*)Alo + (size_t)(b * NTL2 + lt) * 16384;
        const char* pwh = (const char*)Whi;
        const char* pwl = (const char*)Wlo;
#pragma unroll
        for (int it = 0; it < 4; it++) {
            int o4 = (tid + (it << 8)) << 4;
            cp16(sAh + o4, pah + o4);
            cp16(sAl + o4, pal + o4);
        }
#pragma unroll
        for (int it = 0; it < 8; it++) {
            int o4 = (tid + (it << 8)) << 4;
            cp16(sWh + o4, pwh + o4);
            cp16(sWl + o4, pwl + o4);
        }
        asm volatile("cp.async.commit_group;");
    }

    // GN stats finalize + bias table (overlaps the cp.async)
    {
        float ps = 0.f, pss = 0.f;
        if (tid < NTL2) {
            ps = part[(b * NTL2 + tid) * 2];
            pss = part[(b * NTL2 + tid) * 2 + 1];
        }
        s1[tid] = ps; s2[tid] = pss;
        __syncthreads();
        for (int off = 128; off > 0; off >>= 1) {
            if (tid < off) { s1[tid] += s1[tid + off]; s2[tid] += s2[tid + off]; }
            __syncthreads();
        }
        if (tid == 0) {
            const float invCnt = 1.f / (128.f * (float)LQ);
            float m = s1[0] * invCnt;
            float v = s2[0] * invCnt - m * m;
            ctrl[4] = m;
            ctrl[5] = rsqrtf(v + 1e-5f);
        }
        __syncthreads();
        if (tid < 128) {
            float m = ctrl[4], r = ctrl[5];
            ctrl[64 + tid] = ba[tid] - m * r * bb[tid];
        }
    }
    asm volatile("cp.async.wait_group 0;");
    __syncthreads();

    // MMA: 3-term split; acc[2 m-tiles][4 n-tiles][4]
    float acc[2][4][4];
#pragma unroll
    for (int i = 0; i < 2; i++)
#pragma unroll
        for (int j = 0; j < 4; j++)
#pragma unroll
            for (int q = 0; q < 4; q++) acc[i][j][q] = 0.f;

#pragma unroll
    for (int ks = 0; ks < 8; ks++) {
        const int c = (ks << 4) + lcol;
        uint32_t ah[2][4], al[2][4];
#pragma unroll
        for (int i = 0; i < 2; i++) {
            int row = l0w + (i << 4) + lrow;
            uint32_t off = (row << 8) + ((((c >> 3) ^ (row & 7))) << 4);
            ldsm4(ah[i], sAh + off);
            ldsm4(al[i], sAl + off);
        }
        uint32_t bh[2][4], bl[2][4];
#pragma unroll
        for (int j4 = 0; j4 < 2; j4++) {
            int row = o0w + (j4 << 4) + lrow;
            uint32_t off = (row << 8) + ((((c >> 3) ^ (row & 7))) << 4);
            ldsm4(bh[j4], sWh + off);
            ldsm4(bl[j4], sWl + off);
        }
#pragma unroll
        for (int i = 0; i < 2; i++)
#pragma unroll
            for (int j = 0; j < 4; j++) {
                uint32_t b0h = bh[j >> 1][j & 1], b1h = bh[j >> 1][(j & 1) + 2];
                uint32_t b0l = bl[j >> 1][j & 1], b1l = bl[j >> 1][(j & 1) + 2];
                mma16816(acc[i][j], ah[i], b0h, b1h);
                mma16816(acc[i][j], ah[i], b0l, b1l);
                mma16816(acc[i][j], al[i], b0h, b1h);
            }
    }

    // epilogue: GN scale/bias + residual (global, L2-hot)
    const float rstd = ctrl[5];
    const float* sbias = ctrl + 64;
#pragma unroll
    for (int i = 0; i < 2; i++) {
        int lloc = l0w + (i << 4) + (lane >> 2);
        int lb = lt * 64 + lloc;
#pragma unroll
        for (int j = 0; j < 4; j++) {
            int o = o0w + (j << 3) + ((lane & 3) << 1);
            float b0 = sbias[o], b1 = sbias[o + 1];
            size_t off0 = (((size_t)b * LPAD + lb) << 7) + o;
            size_t off1 = off0 + (8 << 7);
            float2 r0 = *(const float2*)(Xres + off0);
            float2 r1 = *(const float2*)(Xres + off1);
            *(float2*)(Y + off0) = make_float2(
                fmaf(rstd, acc[i][j][0], b0) + r0.x,
                fmaf(rstd, acc[i][j][1], b1) + r0.y);
            *(float2*)(Y + off1) = make_float2(
                fmaf(rstd, acc[i][j][2], b0) + r1.x,
                fmaf(rstd, acc[i][j][3], b1) + r1.y);
        }
    }
}

// ---------------- generic tensor-core GEMM, 64x128 tile (compression/expansion) --------
template <int KCH, bool STATS, bool SIG>
__global__ void __launch_bounds__(256, 2) gemm_mma(
    const __nv_bfloat16* __restrict__ Ahi, const __nv_bfloat16* __restrict__ Alo,
    const __nv_bfloat16* __restrict__ Whi, const __nv_bfloat16* __restrict__ Wlo,
    float* __restrict__ Y,
    const float* __restrict__ ba, const float* __restrict__ bb,
    const float* __restrict__ part, int npart, float invCnt) {
    extern __shared__ char smch[];
    float* ctrl = (float*)smch;
    char* tiles = smch + 1024;
    const uint32_t sAh = smem_u32(tiles);
    const uint32_t sAl = sAh + 16384;
    const uint32_t sWh = sAl + 16384;
    const uint32_t sWl = sWh + 32768;
    __shared__ float s1[256], s2[256];

    const int tid = threadIdx.x;
    const int lt = blockIdx.x, ot = blockIdx.y, b = blockIdx.z;
    const int wid = tid >> 5, lane = tid & 31;
    const int wm = wid & 1, wn = wid >> 1;
    const int l0w = wm << 5, o0w = wn << 5;
    const int lrow = (lane & 7) + ((lane >> 3) & 1) * 8;
    const int lcol = (lane >> 4) * 8;

    // A subtile indexing: stored tiles are 128 rows; take half (lt&1)
    const size_t subA = ((size_t)(b * NTL + (lt >> 1)) * KCH) * 32768 + (lt & 1) * 16384;
    auto load_chunk = [&](int kc) {
        const char* pah = (const char*)Ahi + subA + (size_t)kc * 32768;
        const char* pal = (const char*)Alo + subA + (size_t)kc * 32768;
        const char* pwh = (const char*)(Whi + (size_t)(ot * KCH + kc) * 16384);
        const char* pwl = (const char*)(Wlo + (size_t)(ot * KCH + kc) * 16384);
#pragma unroll
        for (int it = 0; it < 4; it++) {
            int o4 = (tid + (it << 8)) << 4;
            cp16(sAh + o4, pah + o4);
            cp16(sAl + o4, pal + o4);
        }
#pragma unroll
        for (int it = 0; it < 8; it++) {
            int o4 = (tid + (it << 8)) << 4;
            cp16(sWh + o4, pwh + o4);
            cp16(sWl + o4, pwl + o4);
        }
        asm volatile("cp.async.commit_group;");
    };
    load_chunk(0);

    float ps = 0.f, pss = 0.f;
    if (STATS) {
        for (int c = tid; c < npart; c += 256) {
            ps += part[(b * npart + c) * 2];
            pss += part[(b * npart + c) * 2 + 1];
        }
    }

    float acc[2][4][4];
#pragma unroll
    for (int i = 0; i < 2; i++)
#pragma unroll
        for (int j = 0; j < 4; j++)
#pragma unroll
            for (int q = 0; q < 4; q++) acc[i][j][q] = 0.f;

    for (int kc = 0; kc < KCH; kc++) {
        asm volatile("cp.async.wait_group 0;");
        __syncthreads();
#pragma unroll
        for (int ks = 0; ks < 8; ks++) {
            const int k0 = ks << 4;
            const int c = k0 + lcol;
            uint32_t ah[2][4], al[2][4];
#pragma unroll
            for (int i = 0; i < 2; i++) {
                int row = l0w + (i << 4) + lrow;
                uint32_t off = (row << 8) + ((((c >> 3) ^ (row & 7))) << 4);
                ldsm4(ah[i], sAh + off);
                ldsm4(al[i], sAl + off);
            }
            uint32_t bh[2][4], bl[2][4];
#pragma unroll
            for (int j4 = 0; j4 < 2; j4++) {
                int row = o0w + (j4 << 4) + lrow;
                uint32_t off = (row << 8) + ((((c >> 3) ^ (row & 7))) << 4);
                ldsm4(bh[j4], sWh + off);
                ldsm4(bl[j4], sWl + off);
            }
#pragma unroll
            for (int i = 0; i < 2; i++)
#pragma unroll
                for (int j = 0; j < 4; j++) {
                    uint32_t b0h = bh[j >> 1][j & 1], b1h = bh[j >> 1][(j & 1) + 2];
                    uint32_t b0l = bl[j >> 1][j & 1], b1l = bl[j >> 1][(j & 1) + 2];
                    mma16816(acc[i][j], ah[i], b0h, b1h);
                    mma16816(acc[i][j], ah[i], b0l, b1l);
                    mma16816(acc[i][j], al[i], b0h, b1h);
                }
        }
        __syncthreads();
        if (kc + 1 < KCH) load_chunk(kc + 1);
    }

    if (STATS) {
        s1[tid] = ps; s2[tid] = pss;
        __syncthreads();
        for (int off = 128; off > 0; off >>= 1) {
            if (tid < off) { s1[tid] += s1[tid + off]; s2[tid] += s2[tid + off]; }
            __syncthreads();
        }
        if (tid == 0) {
            float m = s1[0] * invCnt;
            float v = s2[0] * invCnt - m * m;
            ctrl[4] = m;
            ctrl[5] = rsqrtf(v + 1e-5f);
        }
        __syncthreads();
        if (tid < 128) {
            float m = ctrl[4], r = ctrl[5];
            ctrl[64 + tid] = ba[tid] - m * r * bb[tid];
        }
        __syncthreads();
    }

    const float rstd = STATS ? ctrl[5] : 1.f;
    const float* sbias = ctrl + 64;
    if (!SIG) {
#pragma unroll
        for (int i = 0; i < 2; i++) {
            int lb = lt * 64 + l0w + (i << 4) + (lane >> 2);
#pragma unroll
            for (int j = 0; j < 4; j++) {
                int o = o0w + (j << 3) + ((lane & 3) << 1);
                float b0 = STATS ? sbias[o] : 0.f;
                float b1 = STATS ? sbias[o + 1] : 0.f;
                size_t off0 = (((size_t)b * LPAD + lb) << 7) + o;
                *(float2*)(Y + off0) = make_float2(fmaf(rstd, acc[i][j][0], b0),
                                                   fmaf(rstd, acc[i][j][1], b1));
                *(float2*)(Y + off0 + (8 << 7)) = make_float2(fmaf(rstd, acc[i][j][2], b0),
                                                              fmaf(rstd, acc[i][j][3], b1));
            }
        }
    } else {
        float* stg = (float*)tiles;    // [128 o][68]
        __syncthreads();
#pragma unroll
        for (int i = 0; i < 2; i++) {
            int lloc = l0w + (i << 4) + (lane >> 2);
#pragma unroll
            for (int j = 0; j < 4; j++) {
                int o = o0w + (j << 3) + ((lane & 3) << 1);
                stg[o * 68 + lloc]           = 1.f / (1.f + __expf(-acc[i][j][0]));
                stg[(o + 1) * 68 + lloc]     = 1.f / (1.f + __expf(-acc[i][j][1]));
                stg[o * 68 + lloc + 8]       = 1.f / (1.f + __expf(-acc[i][j][2]));
                stg[(o + 1) * 68 + lloc + 8] = 1.f / (1.f + __expf(-acc[i][j][3]));
            }
        }
        __syncthreads();
        int o = tid >> 1, half = tid & 1;
        float* yb = Y + ((size_t)(b * 1024 + (ot << 7) + o)) * LQ + lt * 64;
#pragma unroll
        for (int g = 0; g < 8; g++) {
            int idx = (half << 5) + (g << 2);
            *(float4*)(yb + idx) = *(float4*)(stg + o * 68 + idx);
        }
    }
}

// ---------------- launch ----------------
extern "C" void kernel_launch(void* const* d_in, const int* in_sizes, int n_in,
                              void* d_out, int out_size) {
    const float* x      = (const float*)d_in[0];
    const float* gn_g   = (const float*)d_in[1];
    const float* gn_b   = (const float*)d_in[2];
    const float* w_comp = (const float*)d_in[3];
    const float* dw_w   = (const float*)d_in[4];
    const float* pr_a   = (const float*)d_in[5];
    const float* tn_g   = (const float*)d_in[6];
    const float* tn_b   = (const float*)d_in[7];
    const float* pw_w   = (const float*)d_in[8];
    const float* w_exp  = (const float*)d_in[9];
    float* out = (float*)d_out;

    float *p_buf0, *p_buf1, *p_wb, *p_wgs, *p_pwb, *p_pwgs, *p_partx, *p_partc;
    __nv_bfloat16 *p_xhi, *p_xlo, *p_hhi, *p_hlo, *p_cwh, *p_cwl, *p_pwh, *p_pwl, *p_ewh, *p_ewl;
    cudaGetSymbolAddress((void**)&p_buf0, g_buf0);
    cudaGetSymbolAddress((void**)&p_buf1, g_buf1);
    cudaGetSymbolAddress((void**)&p_xhi, g_xhi);  cudaGetSymbolAddress((void**)&p_xlo, g_xlo);
    cudaGetSymbolAddress((void**)&p_hhi, g_hhi);  cudaGetSymbolAddress((void**)&p_hlo, g_hlo);
    cudaGetSymbolAddress((void**)&p_cwh, g_cwh);  cudaGetSymbolAddress((void**)&p_cwl, g_cwl);
    cudaGetSymbolAddress((void**)&p_pwh, g_pwh);  cudaGetSymbolAddress((void**)&p_pwl, g_pwl);
    cudaGetSymbolAddress((void**)&p_ewh, g_ewh);  cudaGetSymbolAddress((void**)&p_ewl, g_ewl);
    cudaGetSymbolAddress((void**)&p_wb, g_wb);    cudaGetSymbolAddress((void**)&p_wgs, g_wgs);
    cudaGetSymbolAddress((void**)&p_pwb, g_pwb);  cudaGetSymbolAddress((void**)&p_pwgs, g_pwgs);
    cudaGetSymbolAddress((void**)&p_partx, g_partx);
    cudaGetSymbolAddress((void**)&p_partc, g_partc);

    const int SMT = 1024 + 98304;   // 97 KB dynamic
    cudaFuncSetAttribute(gemm_mma<4, true, false>,
                         cudaFuncAttributeMaxDynamicSharedMemorySize, SMT);
    cudaFuncSetAttribute(gemm_mma<1, false, true>,
                         cudaFuncAttributeMaxDynamicSharedMemorySize, SMT);
    cudaFuncSetAttribute(gemm_pw,
                         cudaFuncAttributeMaxDynamicSharedMemorySize, SMT);
    cudaFuncSetAttribute(xsplit_kernel, cudaFuncAttributeMaxDynamicSharedMemorySize, 65536);

    // weight prep (launches 1-3)
    comp_img_kernel<<<256, 256>>>(w_comp, gn_g, p_cwh, p_cwl);
    sums_wg_kernel<<<128, 256>>>(w_comp, gn_g, gn_b, p_wb, p_wgs);
    pw_img_kernel<<<24, 256>>>(pw_w, tn_g, p_pwh, p_pwl);

    // launch #4: DUMMY gemm_pw replica for ncu visibility (writes only buf1's
    // l<8000 region, fully overwritten by layer 0 below -> output-deterministic)
    gemm_pw<<<dim3(NTL2, 4), 256, SMT>>>(p_hhi, p_hlo, p_pwh, p_pwl,
                                         p_buf0, p_buf1, p_pwb, p_pwgs, p_partc);

    sums_pw_kernel<<<dim3(128, 24), 128>>>(pw_w, tn_g, tn_b, p_pwb, p_pwgs);
    exp_img_kernel<<<8, 256>>>(w_exp, p_ewh, p_ewl);

    // outer GN stats + x transpose/split
    rowstats_kernel<<<dim3(512, 4), 256>>>(x, p_partx);
    xsplit_kernel<<<dim3(NTL, 4), 256, 65536>>>(x, p_xhi, p_xlo);

    // compression: xT @ Wc -> buf0 [b][l][128]   (K=512 via 4 chunks of 128)
    gemm_mma<4, true, false><<<dim3(NTL2, 1, 4), 256, SMT>>>(
        p_xhi, p_xlo, p_cwh, p_cwl, p_buf0, p_wb, p_wgs, p_partx, 512,
        1.f / (512.f * (float)LQ));

    // 24 TCN blocks: single conv pass (split+stats) + monolithic async GEMM
    float* bufs[2] = {p_buf0, p_buf1};
    for (int i = 0; i < 24; i++) {
        int d = 1 << (i & 7);
        float* A = bufs[i & 1];
        float* B = bufs[(i + 1) & 1];
        convsplit_kernel<<<dim3(NTL2, 4), 256>>>(A, dw_w + i * 128 * 3,
                                                 pr_a + i * 128, d,
                                                 p_hhi, p_hlo, p_partc);
        gemm_pw<<<dim3(NTL2, 4), 256, SMT>>>(
            p_hhi, p_hlo, p_pwh + (size_t)i * 16384, p_pwl + (size_t)i * 16384,
            A, B, p_pwb + i * 128, p_pwgs + i * 128, p_partc);
    }

    // split final activation (buf0), then expansion + sigmoid -> d_out
    splitonly_kernel<<<dim3(NTL, 4), 256>>>(p_buf0, p_hhi, p_hlo);
    gemm_mma<1, false, true><<<dim3(NTL2, 8, 4), 256, SMT>>>(
        p_hhi, p_hlo, p_ewh, p_ewl, out, nullptr, nullptr, nullptr, 0, 0.f);
}

// round 17
// speedup vs baseline: 1.5379x; 1.0334x over previous
#include <cuda_runtime.h>
#include <cuda_bf16.h>
#include <math.h>
#include <stdint.h>

#define LQ 8000
#define LPAD 8192
#define NTL 63      // 128-row tiles (compression/expansion path)
#define NTL2 125    // 64-row tiles (pointwise path; 125*64 = 8000 exactly)

// ---------------- device scratch (no allocation allowed) ----------------
__device__ float g_buf0[4 * LPAD * 128];                // activation ping [b][l][c]
__device__ float g_buf1[4 * LPAD * 128];                // activation pong
__device__ __nv_bfloat16 g_xhi[4 * NTL * 4 * 16384];    // xT split tiles (128-row)
__device__ __nv_bfloat16 g_xlo[4 * NTL * 4 * 16384];
__device__ __nv_bfloat16 g_hhi[4 * NTL * 16384];        // conv/final split tiles
__device__ __nv_bfloat16 g_hlo[4 * NTL * 16384];
__device__ __nv_bfloat16 g_cwh[4 * 16384];              // compression W tiles
__device__ __nv_bfloat16 g_cwl[4 * 16384];
__device__ __nv_bfloat16 g_pwh[24 * 16384];             // pointwise W tiles
__device__ __nv_bfloat16 g_pwl[24 * 16384];
__device__ __nv_bfloat16 g_ewh[8 * 16384];              // expansion W tiles
__device__ __nv_bfloat16 g_ewl[8 * 16384];
__device__ float g_wb[128], g_wgs[128];
__device__ float g_pwb[24 * 128], g_pwgs[24 * 128];
__device__ float g_partx[4 * 512 * 2];
__device__ float g_partc[4 * NTL2 * 2];

// ---------------- helpers ----------------
__device__ __forceinline__ int swz_half(int row, int c) {
    return row * 128 + ((((c >> 3) ^ (row & 7)) << 3) | (c & 7));
}
__device__ __forceinline__ uint32_t smem_u32(const void* p) {
    uint32_t a;
    asm("{ .reg .u64 t; cvta.to.shared.u64 t, %1; cvt.u32.u64 %0, t; }" : "=r"(a) : "l"(p));
    return a;
}
__device__ __forceinline__ void cp16(uint32_t dst, const void* src) {
    asm volatile("cp.async.cg.shared.global [%0], [%1], 16;" :: "r"(dst), "l"(src));
}
__device__ __forceinline__ void ldsm4(uint32_t* r, uint32_t addr) {
    asm volatile("ldmatrix.sync.aligned.m8n8.x4.shared.b16 {%0,%1,%2,%3}, [%4];"
                 : "=r"(r[0]), "=r"(r[1]), "=r"(r[2]), "=r"(r[3]) : "r"(addr));
}
__device__ __forceinline__ void mma16816(float* c, const uint32_t* a,
                                         uint32_t b0, uint32_t b1) {
    asm volatile(
        "mma.sync.aligned.m16n8k16.row.col.f32.bf16.bf16.f32 "
        "{%0,%1,%2,%3}, {%4,%5,%6,%7}, {%8,%9}, {%0,%1,%2,%3};"
        : "+f"(c[0]), "+f"(c[1]), "+f"(c[2]), "+f"(c[3])
        : "r"(a[0]), "r"(a[1]), "r"(a[2]), "r"(a[3]), "r"(b0), "r"(b1));
}

// ---------------- weight prep ----------------
__global__ void comp_img_kernel(const float* __restrict__ w, const float* __restrict__ g,
                                __nv_bfloat16* __restrict__ ih, __nv_bfloat16* __restrict__ il) {
    int idx = blockIdx.x * 256 + threadIdx.x;
    int n = idx >> 7, o = idx & 127;
    float wv = w[o * 512 + n] * g[n];
    __nv_bfloat16 hi = __float2bfloat16(wv);
    int pos = (n >> 7) * 16384 + swz_half(o, n & 127);
    ih[pos] = hi;
    il[pos] = __float2bfloat16(wv - __bfloat162float(hi));
}
__global__ void sums_wg_kernel(const float* __restrict__ w, const float* __restrict__ g,
                               const float* __restrict__ beta,
                               float* __restrict__ wb, float* __restrict__ wgs) {
    int o = blockIdx.x, tid = threadIdx.x;
    float w1 = w[o * 512 + tid], w2 = w[o * 512 + tid + 256];
    float sb = w1 * beta[tid] + w2 * beta[tid + 256];
    float sg = w1 * g[tid] + w2 * g[tid + 256];
    __shared__ float r1[256], r2[256];
    r1[tid] = sb; r2[tid] = sg;
    __syncthreads();
    for (int off = 128; off > 0; off >>= 1) {
        if (tid < off) { r1[tid] += r1[tid + off]; r2[tid] += r2[tid + off]; }
        __syncthreads();
    }
    if (tid == 0) { wb[o] = r1[0]; wgs[o] = r2[0]; }
}
__global__ void pw_img_kernel(const float* __restrict__ pw, const float* __restrict__ tg,
                              __nv_bfloat16* __restrict__ ih, __nv_bfloat16* __restrict__ il) {
    int i = blockIdx.x;
    for (int it = 0; it < 64; it++) {
        int idx = threadIdx.x + (it << 8);
        int o = idx >> 7, c = idx & 127;
        float wv = pw[(size_t)i * 16384 + o * 128 + c] * tg[i * 128 + c];
        __nv_bfloat16 hi = __float2bfloat16(wv);
        int pos = i * 16384 + swz_half(o, c);
        ih[pos] = hi;
        il[pos] = __float2bfloat16(wv - __bfloat162float(hi));
    }
}
__global__ void sums_pw_kernel(const float* __restrict__ pw, const float* __restrict__ tg,
                               const float* __restrict__ tb,
                               float* __restrict__ pwb, float* __restrict__ pwgs) {
    int o = blockIdx.x, i = blockIdx.y, c = threadIdx.x;
    float wv = pw[(size_t)(i * 128 + o) * 128 + c];
    float sb = wv * tb[i * 128 + c];
    float sg = wv * tg[i * 128 + c];
    __shared__ float r1[128], r2[128];
    r1[c] = sb; r2[c] = sg;
    __syncthreads();
    for (int off = 64; off > 0; off >>= 1) {
        if (c < off) { r1[c] += r1[c + off]; r2[c] += r2[c + off]; }
        __syncthreads();
    }
    if (c == 0) { pwb[i * 128 + o] = r1[0]; pwgs[i * 128 + o] = r2[0]; }
}
__global__ void exp_img_kernel(const float* __restrict__ we,
                               __nv_bfloat16* __restrict__ ih, __nv_bfloat16* __restrict__ il) {
    int t = blockIdx.x;
    for (int it = 0; it < 64; it++) {
        int idx = threadIdx.x + (it << 8);
        int o = idx >> 7, c = idx & 127;
        float wv = we[(size_t)((t << 7) + o) * 128 + c];
        __nv_bfloat16 hi = __float2bfloat16(wv);
        int pos = t * 16384 + swz_half(o, c);
        ih[pos] = hi;
        il[pos] = __float2bfloat16(wv - __bfloat162float(hi));
    }
}

// ---------------- per-row stats of x ----------------
__global__ void rowstats_kernel(const float* __restrict__ src, float* __restrict__ part) {
    int c = blockIdx.x, b = blockIdx.y;
    const float4* row = (const float4*)(src + ((size_t)b * 512 + c) * LQ);
    float s = 0.f, ss = 0.f;
    for (int i = threadIdx.x; i < LQ / 4; i += 256) {
        float4 v = row[i];
        s += v.x + v.y + v.z + v.w;
        ss += v.x * v.x + v.y * v.y + v.z * v.z + v.w * v.w;
    }
    __shared__ float rs[256], rss[256];
    rs[threadIdx.x] = s; rss[threadIdx.x] = ss;
    __syncthreads();
    for (int off = 128; off > 0; off >>= 1) {
        if ((int)threadIdx.x < off) {
            rs[threadIdx.x] += rs[threadIdx.x + off];
            rss[threadIdx.x] += rss[threadIdx.x + off];
        }
        __syncthreads();
    }
    if (threadIdx.x == 0) {
        part[(b * 512 + c) * 2 + 0] = rs[0];
        part[(b * 512 + c) * 2 + 1] = rss[0];
    }
}

// ---------------- transpose+split x into swizzled bf16 tiles (128-row) ----------------
__global__ void __launch_bounds__(256) xsplit_kernel(
    const float* __restrict__ x,
    __nv_bfloat16* __restrict__ Xhi, __nv_bfloat16* __restrict__ Xlo) {
    extern __shared__ char sm[];
    __nv_bfloat16* th = (__nv_bfloat16*)sm;
    __nv_bfloat16* tl = (__nv_bfloat16*)(sm + 32768);
    int t = blockIdx.x, b = blockIdx.y, tid = threadIdx.x;
    int ll = tid & 127, nh = tid >> 7;
    for (int kc = 0; kc < 4; kc++) {
        for (int i = 0; i < 64; i++) {
            int n = (i << 1) + nh;
            int l = t * 128 + ll;
            float v = (l < LQ) ? x[((size_t)(b * 512 + kc * 128 + n)) * LQ + l] : 0.f;
            __nv_bfloat16 hi = __float2bfloat16(v);
            int pos = swz_half(ll, n);
            th[pos] = hi;
            tl[pos] = __float2bfloat16(v - __bfloat162float(hi));
        }
        __syncthreads();
        float4* gh = (float4*)(Xhi + ((size_t)((b * NTL + t) * 4 + kc)) * 16384);
        float4* gl = (float4*)(Xlo + ((size_t)((b * NTL + t) * 4 + kc)) * 16384);
        for (int i = tid; i < 2048; i += 256) { gh[i] = ((float4*)th)[i]; gl[i] = ((float4*)tl)[i]; }
        __syncthreads();
    }
}

// ---------------- conv + PReLU + split + stats, ONE pass (64-row tiles) ----------------
__global__ void __launch_bounds__(256) convsplit_kernel(
    const float* __restrict__ X, const float* __restrict__ dw3,
    const float* __restrict__ pra, int d,
    __nv_bfloat16* __restrict__ Hhi, __nv_bfloat16* __restrict__ Hlo,
    float* __restrict__ part) {
    int t = blockIdx.x, b = blockIdx.y, tid = threadIdx.x;
    int cg = (tid & 31) << 2;
    int r0 = tid >> 5;
    float w0v[4], w1v[4], w2v[4], av[4];
#pragma unroll
    for (int j = 0; j < 4; j++) {
        w0v[j] = dw3[(cg + j) * 3 + 0];
        w1v[j] = dw3[(cg + j) * 3 + 1];
        w2v[j] = dw3[(cg + j) * 3 + 2];
        av[j]  = pra[cg + j];
    }
    const float* Xb = X + ((size_t)b * LPAD) * 128;
    size_t tbase = (size_t)(b * NTL2 + t) * 8192;
    int d2 = d << 1;
    float s = 0.f, ss = 0.f;
    const bool interior = (t * 64) >= d2;
#pragma unroll
    for (int k = 0; k < 8; k++) {
        int ll = (k << 3) + r0;
        int l = t * 64 + ll;
        size_t idx = ((size_t)l << 7) + cg;
        float4 x2 = *(const float4*)(Xb + idx);
        float4 x1, x0;
        if (interior) {
            x1 = *(const float4*)(Xb + idx - ((size_t)d << 7));
            x0 = *(const float4*)(Xb + idx - ((size_t)d2 << 7));
        } else {
            x1 = make_float4(0.f, 0.f, 0.f, 0.f);
            x0 = make_float4(0.f, 0.f, 0.f, 0.f);
            if (l >= d)  x1 = *(const float4*)(Xb + idx - ((size_t)d << 7));
            if (l >= d2) x0 = *(const float4*)(Xb + idx - ((size_t)d2 << 7));
        }
        float v[4];
        v[0] = w2v[0] * x2.x + w1v[0] * x1.x + w0v[0] * x0.x;
        v[1] = w2v[1] * x2.y + w1v[1] * x1.y + w0v[1] * x0.y;
        v[2] = w2v[2] * x2.z + w1v[2] * x1.z + w0v[2] * x0.z;
        v[3] = w2v[3] * x2.w + w1v[3] * x1.w + w0v[3] * x0.w;
        uint32_t hp[2], lp[2];
#pragma unroll
        for (int h = 0; h < 2; h++) {
            float a0 = v[2 * h], a1 = v[2 * h + 1];
            a0 = a0 > 0.f ? a0 : av[2 * h] * a0;
            a1 = a1 > 0.f ? a1 : av[2 * h + 1] * a1;
            s += a0 + a1; ss += a0 * a0 + a1 * a1;
            __nv_bfloat16 h0 = __float2bfloat16(a0), h1 = __float2bfloat16(a1);
            __nv_bfloat16 l0 = __float2bfloat16(a0 - __bfloat162float(h0));
            __nv_bfloat16 l1 = __float2bfloat16(a1 - __bfloat162float(h1));
            hp[h] = ((uint32_t)*(uint16_t*)&h1 << 16) | *(uint16_t*)&h0;
            lp[h] = ((uint32_t)*(uint16_t*)&l1 << 16) | *(uint16_t*)&l0;
        }
        int hidx = (ll << 7) + ((((cg >> 3) ^ (ll & 7)) << 3) | (cg & 7));
        *(uint2*)(Hhi + tbase + hidx) = make_uint2(hp[0], hp[1]);
        *(uint2*)(Hlo + tbase + hidx) = make_uint2(lp[0], lp[1]);
    }
    __shared__ float rs[256], rss[256];
    rs[tid] = s; rss[tid] = ss;
    __syncthreads();
    for (int off = 128; off > 0; off >>= 1) {
        if (tid < off) { rs[tid] += rs[tid + off]; rss[tid] += rss[tid + off]; }
        __syncthreads();
    }
    if (tid == 0) {
        part[(b * NTL2 + t) * 2 + 0] = rs[0];
        part[(b * NTL2 + t) * 2 + 1] = rss[0];
    }
}

// ---------------- split-only (final activation -> 128-row tiles for expansion) ---------
__global__ void __launch_bounds__(256) splitonly_kernel(
    const float* __restrict__ X,
    __nv_bfloat16* __restrict__ Hhi, __nv_bfloat16* __restrict__ Hlo) {
    int t = blockIdx.x, b = blockIdx.y, tid = threadIdx.x;
    int c = tid & 127, lh = tid >> 7;
    const float* Xb = X + ((size_t)b * LPAD) * 128;
    size_t tbase = ((size_t)(b * NTL + t)) * 16384;
#pragma unroll 4
    for (int i = 0; i < 64; i++) {
        int ll = (i << 1) + lh;
        float v = Xb[(((size_t)(t * 128 + ll)) << 7) + c];
        __nv_bfloat16 hi = __float2bfloat16(v);
        int pos = swz_half(ll, c);
        Hhi[tbase + pos] = hi;
        Hlo[tbase + pos] = __float2bfloat16(v - __bfloat162float(hi));
    }
}

// ---------------- pointwise GEMM: 64l x 64o tile, 65KB smem, 3 CTAs/SM ----------------
// 128 threads = 4 warps (2 m x 2 n), each warp 32l x 32o (same inner code as before).
// grid (125, 2, 4): ot = blockIdx.y selects the 64-o half of W.
__global__ void __launch_bounds__(128, 3) gemm_pw(
    const __nv_bfloat16* __restrict__ Ahi, const __nv_bfloat16* __restrict__ Alo,
    const __nv_bfloat16* __restrict__ Whi, const __nv_bfloat16* __restrict__ Wlo,
    const float* __restrict__ Xres, float* __restrict__ Y,
    const float* __restrict__ ba, const float* __restrict__ bb,
    const float* __restrict__ part) {
    extern __shared__ char smch[];
    float* ctrl = (float*)smch;                 // [4]=mean [5]=rstd, [64..127]=bias(64)
    char* tiles = smch + 1024;
    const uint32_t sAh = smem_u32(tiles);            // 16 KB (64 rows x 256B)
    const uint32_t sAl = sAh + 16384;
    const uint32_t sWh = sAl + 16384;                // 16 KB (64 rows x 256B)
    const uint32_t sWl = sWh + 16384;
    __shared__ float s1[128], s2[128];

    const int tid = threadIdx.x;
    const int lt = blockIdx.x, ot = blockIdx.y, b = blockIdx.z;
    const int wid = tid >> 5, lane = tid & 31;
    const int wm = wid & 1, wn = wid >> 1;           // 2 m-warps x 2 n-warps
    const int l0w = wm << 5, o0w = wn << 5;
    const int lrow = (lane & 7) + ((lane >> 3) & 1) * 8;
    const int lcol = (lane >> 4) * 8;

    // issue all tile copies immediately (A 32 KB + W-half 32 KB)
    {
        const char* pah = (const char*)Ahi + (size_t)(b * NTL2 + lt) * 16384;
        const char* pal = (const char*)Alo + (size_t)(b * NTL2 + lt) * 16384;
        const char* pwh = (const char*)Whi + (ot << 14);
        const char* pwl = (const char*)Wlo + (ot << 14);
#pragma unroll
        for (int it = 0; it < 8; it++) {
            int o4 = (tid + (it << 7)) << 4;
            cp16(sAh + o4, pah + o4);
            cp16(sAl + o4, pal + o4);
            cp16(sWh + o4, pwh + o4);
            cp16(sWl + o4, pwl + o4);
        }
        asm volatile("cp.async.commit_group;");
    }

    // GN stats finalize + bias table (overlaps the cp.async)
    {
        float ps = 0.f, pss = 0.f;
        if (tid < NTL2) {
            ps = part[(b * NTL2 + tid) * 2];
            pss = part[(b * NTL2 + tid) * 2 + 1];
        }
        s1[tid] = ps; s2[tid] = pss;
        __syncthreads();
        for (int off = 64; off > 0; off >>= 1) {
            if (tid < off) { s1[tid] += s1[tid + off]; s2[tid] += s2[tid + off]; }
            __syncthreads();
        }
        if (tid == 0) {
            const float invCnt = 1.f / (128.f * (float)LQ);
            float m = s1[0] * invCnt;
            float v = s2[0] * invCnt - m * m;
            ctrl[4] = m;
            ctrl[5] = rsqrtf(v + 1e-5f);
        }
        __syncthreads();
        if (tid < 64) {
            int o = (ot << 6) + tid;
            float m = ctrl[4], r = ctrl[5];
            ctrl[64 + tid] = ba[o] - m * r * bb[o];
        }
    }
    asm volatile("cp.async.wait_group 0;");
    __syncthreads();

    // MMA: 3-term split; acc[2 m-tiles][4 n-subtiles][4]  (per warp: 32l x 32o)
    float acc[2][4][4];
#pragma unroll
    for (int i = 0; i < 2; i++)
#pragma unroll
        for (int j = 0; j < 4; j++)
#pragma unroll
            for (int q = 0; q < 4; q++) acc[i][j][q] = 0.f;

#pragma unroll
    for (int ks = 0; ks < 8; ks++) {
        const int c = (ks << 4) + lcol;
        uint32_t ah[2][4], al[2][4];
#pragma unroll
        for (int i = 0; i < 2; i++) {
            int row = l0w + (i << 4) + lrow;
            uint32_t off = (row << 8) + ((((c >> 3) ^ (row & 7))) << 4);
            ldsm4(ah[i], sAh + off);
            ldsm4(al[i], sAl + off);
        }
        uint32_t bh[2][4], bl[2][4];
#pragma unroll
        for (int j4 = 0; j4 < 2; j4++) {
            int row = o0w + (j4 << 4) + lrow;
            uint32_t off = (row << 8) + ((((c >> 3) ^ (row & 7))) << 4);
            ldsm4(bh[j4], sWh + off);
            ldsm4(bl[j4], sWl + off);
        }
#pragma unroll
        for (int i = 0; i < 2; i++)
#pragma unroll
            for (int j = 0; j < 4; j++) {
                uint32_t b0h = bh[j >> 1][j & 1], b1h = bh[j >> 1][(j & 1) + 2];
                uint32_t b0l = bl[j >> 1][j & 1], b1l = bl[j >> 1][(j & 1) + 2];
                mma16816(acc[i][j], ah[i], b0h, b1h);
                mma16816(acc[i][j], ah[i], b0l, b1l);
                mma16816(acc[i][j], al[i], b0h, b1h);
            }
    }

    // epilogue: GN scale/bias + residual (global, L2-hot)
    const float rstd = ctrl[5];
    const float* sbias = ctrl + 64;
#pragma unroll
    for (int i = 0; i < 2; i++) {
        int lloc = l0w + (i << 4) + (lane >> 2);
        int lb = lt * 64 + lloc;
#pragma unroll
        for (int j = 0; j < 4; j++) {
            int ol = o0w + (j << 3) + ((lane & 3) << 1);   // local 0..63
            int o = (ot << 6) + ol;
            float b0 = sbias[ol], b1 = sbias[ol + 1];
            size_t off0 = (((size_t)b * LPAD + lb) << 7) + o;
            size_t off1 = off0 + (8 << 7);
            float2 r0 = *(const float2*)(Xres + off0);
            float2 r1 = *(const float2*)(Xres + off1);
            *(float2*)(Y + off0) = make_float2(
                fmaf(rstd, acc[i][j][0], b0) + r0.x,
                fmaf(rstd, acc[i][j][1], b1) + r0.y);
            *(float2*)(Y + off1) = make_float2(
                fmaf(rstd, acc[i][j][2], b0) + r1.x,
                fmaf(rstd, acc[i][j][3], b1) + r1.y);
        }
    }
}

// ---------------- generic tensor-core GEMM, 64x128 tile (compression/expansion) --------
template <int KCH, bool STATS, bool SIG>
__global__ void __launch_bounds__(256, 2) gemm_mma(
    const __nv_bfloat16* __restrict__ Ahi, const __nv_bfloat16* __restrict__ Alo,
    const __nv_bfloat16* __restrict__ Whi, const __nv_bfloat16* __restrict__ Wlo,
    float* __restrict__ Y,
    const float* __restrict__ ba, const float* __restrict__ bb,
    const float* __restrict__ part, int npart, float invCnt) {
    extern __shared__ char smch[];
    float* ctrl = (float*)smch;
    char* tiles = smch + 1024;
    const uint32_t sAh = smem_u32(tiles);
    const uint32_t sAl = sAh + 16384;
    const uint32_t sWh = sAl + 16384;
    const uint32_t sWl = sWh + 32768;
    __shared__ float s1[256], s2[256];

    const int tid = threadIdx.x;
    const int lt = blockIdx.x, ot = blockIdx.y, b = blockIdx.z;
    const int wid = tid >> 5, lane = tid & 31;
    const int wm = wid & 1, wn = wid >> 1;
    const int l0w = wm << 5, o0w = wn << 5;
    const int lrow = (lane & 7) + ((lane >> 3) & 1) * 8;
    const int lcol = (lane >> 4) * 8;

    // A subtile indexing: stored tiles are 128 rows; take half (lt&1)
    const size_t subA = ((size_t)(b * NTL + (lt >> 1)) * KCH) * 32768 + (lt & 1) * 16384;
    auto load_chunk = [&](int kc) {
        const char* pah = (const char*)Ahi + subA + (size_t)kc * 32768;
        const char* pal = (const char*)Alo + subA + (size_t)kc * 32768;
        const char* pwh = (const char*)(Whi + (size_t)(ot * KCH + kc) * 16384);
        const char* pwl = (const char*)(Wlo + (size_t)(ot * KCH + kc) * 16384);
#pragma unroll
        for (int it = 0; it < 4; it++) {
            int o4 = (tid + (it << 8)) << 4;
            cp16(sAh + o4, pah + o4);
            cp16(sAl + o4, pal + o4);
        }
#pragma unroll
        for (int it = 0; it < 8; it++) {
            int o4 = (tid + (it << 8)) << 4;
            cp16(sWh + o4, pwh + o4);
            cp16(sWl + o4, pwl + o4);
        }
        asm volatile("cp.async.commit_group;");
    };
    load_chunk(0);

    float ps = 0.f, pss = 0.f;
    if (STATS) {
        for (int c = tid; c < npart; c += 256) {
            ps += part[(b * npart + c) * 2];
            pss += part[(b * npart + c) * 2 + 1];
        }
    }

    float acc[2][4][4];
#pragma unroll
    for (int i = 0; i < 2; i++)
#pragma unroll
        for (int j = 0; j < 4; j++)
#pragma unroll
            for (int q = 0; q < 4; q++) acc[i][j][q] = 0.f;

    for (int kc = 0; kc < KCH; kc++) {
        asm volatile("cp.async.wait_group 0;");
        __syncthreads();
#pragma unroll
        for (int ks = 0; ks < 8; ks++) {
            const int k0 = ks << 4;
            const int c = k0 + lcol;
            uint32_t ah[2][4], al[2][4];
#pragma unroll
            for (int i = 0; i < 2; i++) {
                int row = l0w + (i << 4) + lrow;
                uint32_t off = (row << 8) + ((((c >> 3) ^ (row & 7))) << 4);
                ldsm4(ah[i], sAh + off);
                ldsm4(al[i], sAl + off);
            }
            uint32_t bh[2][4], bl[2][4];
#pragma unroll
            for (int j4 = 0; j4 < 2; j4++) {
                int row = o0w + (j4 << 4) + lrow;
                uint32_t off = (row << 8) + ((((c >> 3) ^ (row & 7))) << 4);
                ldsm4(bh[j4], sWh + off);
                ldsm4(bl[j4], sWl + off);
            }
#pragma unroll
            for (int i = 0; i < 2; i++)
#pragma unroll
                for (int j = 0; j < 4; j++) {
                    uint32_t b0h = bh[j >> 1][j & 1], b1h = bh[j >> 1][(j & 1) + 2];
                    uint32_t b0l = bl[j >> 1][j & 1], b1l = bl[j >> 1][(j & 1) + 2];
                    mma16816(acc[i][j], ah[i], b0h, b1h);
                    mma16816(acc[i][j], ah[i], b0l, b1l);
                    mma16816(acc[i][j], al[i], b0h, b1h);
                }
        }
        __syncthreads();
        if (kc + 1 < KCH) load_chunk(kc + 1);
    }

    if (STATS) {
        s1[tid] = ps; s2[tid] = pss;
        __syncthreads();
        for (int off = 128; off > 0; off >>= 1) {
            if (tid < off) { s1[tid] += s1[tid + off]; s2[tid] += s2[tid + off]; }
            __syncthreads();
        }
        if (tid == 0) {
            float m = s1[0] * invCnt;
            float v = s2[0] * invCnt - m * m;
            ctrl[4] = m;
            ctrl[5] = rsqrtf(v + 1e-5f);
        }
        __syncthreads();
        if (tid < 128) {
            float m = ctrl[4], r = ctrl[5];
            ctrl[64 + tid] = ba[tid] - m * r * bb[tid];
        }
        __syncthreads();
    }

    const float rstd = STATS ? ctrl[5] : 1.f;
    const float* sbias = ctrl + 64;
    if (!SIG) {
#pragma unroll
        for (int i = 0; i < 2; i++) {
            int lb = lt * 64 + l0w + (i << 4) + (lane >> 2);
#pragma unroll
            for (int j = 0; j < 4; j++) {
                int o = o0w + (j << 3) + ((lane & 3) << 1);
                float b0 = STATS ? sbias[o] : 0.f;
                float b1 = STATS ? sbias[o + 1] : 0.f;
                size_t off0 = (((size_t)b * LPAD + lb) << 7) + o;
                *(float2*)(Y + off0) = make_float2(fmaf(rstd, acc[i][j][0], b0),
                                                   fmaf(rstd, acc[i][j][1], b1));
                *(float2*)(Y + off0 + (8 << 7)) = make_float2(fmaf(rstd, acc[i][j][2], b0),
                                                              fmaf(rstd, acc[i][j][3], b1));
            }
        }
    } else {
        float* stg = (float*)tiles;    // [128 o][68]
        __syncthreads();
#pragma unroll
        for (int i = 0; i < 2; i++) {
            int lloc = l0w + (i << 4) + (lane >> 2);
#pragma unroll
            for (int j = 0; j < 4; j++) {
                int o = o0w + (j << 3) + ((lane & 3) << 1);
                stg[o * 68 + lloc]           = 1.f / (1.f + __expf(-acc[i][j][0]));
                stg[(o + 1) * 68 + lloc]     = 1.f / (1.f + __expf(-acc[i][j][1]));
                stg[o * 68 + lloc + 8]       = 1.f / (1.f + __expf(-acc[i][j][2]));
                stg[(o + 1) * 68 + lloc + 8] = 1.f / (1.f + __expf(-acc[i][j][3]));
            }
        }
        __syncthreads();
        int o = tid >> 1, half = tid & 1;
        float* yb = Y + ((size_t)(b * 1024 + (ot << 7) + o)) * LQ + lt * 64;
#pragma unroll
        for (int g = 0; g < 8; g++) {
            int idx = (half << 5) + (g << 2);
            *(float4*)(yb + idx) = *(float4*)(stg + o * 68 + idx);
        }
    }
}

// ---------------- launch ----------------
extern "C" void kernel_launch(void* const* d_in, const int* in_sizes, int n_in,
                              void* d_out, int out_size) {
    const float* x      = (const float*)d_in[0];
    const float* gn_g   = (const float*)d_in[1];
    const float* gn_b   = (const float*)d_in[2];
    const float* w_comp = (const float*)d_in[3];
    const float* dw_w   = (const float*)d_in[4];
    const float* pr_a   = (const float*)d_in[5];
    const float* tn_g   = (const float*)d_in[6];
    const float* tn_b   = (const float*)d_in[7];
    const float* pw_w   = (const float*)d_in[8];
    const float* w_exp  = (const float*)d_in[9];
    float* out = (float*)d_out;

    float *p_buf0, *p_buf1, *p_wb, *p_wgs, *p_pwb, *p_pwgs, *p_partx, *p_partc;
    __nv_bfloat16 *p_xhi, *p_xlo, *p_hhi, *p_hlo, *p_cwh, *p_cwl, *p_pwh, *p_pwl, *p_ewh, *p_ewl;
    cudaGetSymbolAddress((void**)&p_buf0, g_buf0);
    cudaGetSymbolAddress((void**)&p_buf1, g_buf1);
    cudaGetSymbolAddress((void**)&p_xhi, g_xhi);  cudaGetSymbolAddress((void**)&p_xlo, g_xlo);
    cudaGetSymbolAddress((void**)&p_hhi, g_hhi);  cudaGetSymbolAddress((void**)&p_hlo, g_hlo);
    cudaGetSymbolAddress((void**)&p_cwh, g_cwh);  cudaGetSymbolAddress((void**)&p_cwl, g_cwl);
    cudaGetSymbolAddress((void**)&p_pwh, g_pwh);  cudaGetSymbolAddress((void**)&p_pwl, g_pwl);
    cudaGetSymbolAddress((void**)&p_ewh, g_ewh);  cudaGetSymbolAddress((void**)&p_ewl, g_ewl);
    cudaGetSymbolAddress((void**)&p_wb, g_wb);    cudaGetSymbolAddress((void**)&p_wgs, g_wgs);
    cudaGetSymbolAddress((void**)&p_pwb, g_pwb);  cudaGetSymbolAddress((void**)&p_pwgs, g_pwgs);
    cudaGetSymbolAddress((void**)&p_partx, g_partx);
    cudaGetSymbolAddress((void**)&p_partc, g_partc);

    const int SMT = 1024 + 98304;   // 97 KB dynamic (gemm_mma)
    const int SMP = 1024 + 65536;   // 65 KB dynamic (gemm_pw)
    cudaFuncSetAttribute(gemm_mma<4, true, false>,
                         cudaFuncAttributeMaxDynamicSharedMemorySize, SMT);
    cudaFuncSetAttribute(gemm_mma<1, false, true>,
                         cudaFuncAttributeMaxDynamicSharedMemorySize, SMT);
    cudaFuncSetAttribute(gemm_pw,
                         cudaFuncAttributeMaxDynamicSharedMemorySize, SMP);
    cudaFuncSetAttribute(xsplit_kernel, cudaFuncAttributeMaxDynamicSharedMemorySize, 65536);

    // weight prep (launches 1-3)
    comp_img_kernel<<<256, 256>>>(w_comp, gn_g, p_cwh, p_cwl);
    sums_wg_kernel<<<128, 256>>>(w_comp, gn_g, gn_b, p_wb, p_wgs);
    pw_img_kernel<<<24, 256>>>(pw_w, tn_g, p_pwh, p_pwl);

    // launch #4: DUMMY gemm_pw replica for ncu visibility (writes only buf1's
    // l<8000 region, fully overwritten by layer 0 below -> output-deterministic)
    gemm_pw<<<dim3(NTL2, 2, 4), 128, SMP>>>(p_hhi, p_hlo, p_pwh, p_pwl,
                                            p_buf0, p_buf1, p_pwb, p_pwgs, p_partc);

    sums_pw_kernel<<<dim3(128, 24), 128>>>(pw_w, tn_g, tn_b, p_pwb, p_pwgs);
    exp_img_kernel<<<8, 256>>>(w_exp, p_ewh, p_ewl);

    // outer GN stats + x transpose/split
    rowstats_kernel<<<dim3(512, 4), 256>>>(x, p_partx);
    xsplit_kernel<<<dim3(NTL, 4), 256, 65536>>>(x, p_xhi, p_xlo);

    // compression: xT @ Wc -> buf0 [b][l][128]   (K=512 via 4 chunks of 128)
    gemm_mma<4, true, false><<<dim3(NTL2, 1, 4), 256, SMT>>>(
        p_xhi, p_xlo, p_cwh, p_cwl, p_buf0, p_wb, p_wgs, p_partx, 512,
        1.f / (512.f * (float)LQ));

    // 24 TCN blocks: single conv pass (split+stats) + 64x64 async GEMM
    float* bufs[2] = {p_buf0, p_buf1};
    for (int i = 0; i < 24; i++) {
        int d = 1 << (i & 7);
        float* A = bufs[i & 1];
        float* B = bufs[(i + 1) & 1];
        convsplit_kernel<<<dim3(NTL2, 4), 256>>>(A, dw_w + i * 128 * 3,
                                                 pr_a + i * 128, d,
                                                 p_hhi, p_hlo, p_partc);
        gemm_pw<<<dim3(NTL2, 2, 4), 128, SMP>>>(
            p_hhi, p_hlo, p_pwh + (size_t)i * 16384, p_pwl + (size_t)i * 16384,
            A, B, p_pwb + i * 128, p_pwgs + i * 128, p_partc);
    }

    // split final activation (buf0), then expansion + sigmoid -> d_out
    splitonly_kernel<<<dim3(NTL, 4), 256>>>(p_buf0, p_hhi, p_hlo);
    gemm_mma<1, false, true><<<dim3(NTL2, 8, 4), 256, SMT>>>(
        p_hhi, p_hlo, p_ewh, p_ewl, out, nullptr, nullptr, nullptr, 0, 0.f);
}